// round 3
// baseline (speedup 1.0000x reference)
#include <cuda_runtime.h>

#define N_    4096
#define C_    128
#define H_    128
#define O_    64
#define E_    65536
#define WPR   128                 // 32-bit words per mask row (4096/32)
#define HALF_ 8388608             // N*N/2 for threefry pairing
#define TOPK_ 10

// ---------------- scratch (static device globals; no allocation) ----------------
static __device__ unsigned g_Abits[N_ * WPR];          // 2 MB adjacency bitmask
static __device__ unsigned g_Mbits[N_ * WPR];          // 2 MB keep-mask bitmask
static __device__ float    g_big[(size_t)N_ * N_];     // 64 MB: sim, then dense Mf
static __device__ float    g_xn [N_ * C_];
static __device__ float    g_xnT[C_ * N_];
static __device__ float    g_Ax [N_ * C_];
static __device__ float    g_A2x[N_ * C_];
static __device__ float    g_agg[N_ * C_];
static __device__ float    g_fused[N_ * C_];
static __device__ float    g_h1[N_ * H_];
static __device__ float    g_h2[N_ * H_];
static __device__ int      g_topk[N_ * TOPK_];
static __device__ float    g_deg[N_];

// ---------------- helpers ----------------
__global__ void k_clear_bits() {
    int i = blockIdx.x * blockDim.x + threadIdx.x;
    if (i < N_ * WPR) g_Abits[i] = 0u;
}

// edge_index is int32 (JAX x64 disabled downgrades int64 -> int32), layout [2, E]
__global__ void k_scatter_edges(const int* __restrict__ ei) {
    int i = blockIdx.x * blockDim.x + threadIdx.x;
    if (i >= E_) return;
    int s = ei[i];
    int d = ei[E_ + i];
    atomicOr(&g_Abits[s * WPR + (d >> 5)], 1u << (d & 31));
}

// xn = x / (||x|| + 1e-8); one warp per row
__global__ void k_rownorm(const float* __restrict__ x) {
    int g    = blockIdx.x * blockDim.x + threadIdx.x;
    int row  = g >> 5;
    int lane = g & 31;
    if (row >= N_) return;
    const float4* xr = reinterpret_cast<const float4*>(x + (size_t)row * C_);
    float4 v = xr[lane];
    float s = v.x * v.x + v.y * v.y + v.z * v.z + v.w * v.w;
    #pragma unroll
    for (int o = 16; o; o >>= 1) s += __shfl_xor_sync(0xffffffffu, s, o);
    float inv = 1.0f / (sqrtf(s) + 1e-8f);
    float4 r = make_float4(v.x * inv, v.y * inv, v.z * inv, v.w * inv);
    reinterpret_cast<float4*>(g_xn + (size_t)row * C_)[lane] = r;
}

__global__ void k_transpose(const float* __restrict__ in, float* __restrict__ out) {
    // in [N_, C_] -> out [C_, N_]
    __shared__ float t[32][33];
    int c0 = blockIdx.x * 32, r0 = blockIdx.y * 32;
    int tx = threadIdx.x, ty = threadIdx.y; // 32 x 8
    #pragma unroll
    for (int i = 0; i < 4; i++)
        t[ty + 8 * i][tx] = in[(size_t)(r0 + ty + 8 * i) * C_ + c0 + tx];
    __syncthreads();
    #pragma unroll
    for (int i = 0; i < 4; i++)
        out[(size_t)(c0 + ty + 8 * i) * N_ + r0 + tx] = t[tx][ty + 8 * i];
}

// ---------------- generic SIMT fp32 GEMM: C[M,Nc] = A[M,K] * B[K,Nc] ----------------
template<int BM, int BN, int BK, int TM, int TN>
__global__ void k_gemm(const float* __restrict__ A, const float* __restrict__ B,
                       float* __restrict__ C, int M, int Nc, int K,
                       const float* __restrict__ rowdiv) {
    __shared__ float As[BM][BK + 1];
    __shared__ float Bs[BK][BN];
    const int nth = (BM / TM) * (BN / TN);
    int tid = threadIdx.x;
    int tx = tid % (BN / TN);
    int ty = tid / (BN / TN);
    int row0 = blockIdx.y * BM, col0 = blockIdx.x * BN;
    float acc[TM][TN];
    #pragma unroll
    for (int i = 0; i < TM; i++)
        #pragma unroll
        for (int j = 0; j < TN; j++) acc[i][j] = 0.f;

    for (int k0 = 0; k0 < K; k0 += BK) {
        for (int i = tid; i < BM * BK; i += nth) {
            int m = i / BK, kk = i % BK;
            As[m][kk] = A[(size_t)(row0 + m) * K + k0 + kk];
        }
        for (int i = tid; i < BK * BN; i += nth) {
            int kk = i / BN, n = i % BN;
            Bs[kk][n] = B[(size_t)(k0 + kk) * Nc + col0 + n];
        }
        __syncthreads();
        #pragma unroll
        for (int kk = 0; kk < BK; kk++) {
            float a[TM], b[TN];
            #pragma unroll
            for (int i = 0; i < TM; i++) a[i] = As[ty * TM + i][kk];
            #pragma unroll
            for (int j = 0; j < TN; j++) b[j] = Bs[kk][tx * TN + j];
            #pragma unroll
            for (int i = 0; i < TM; i++)
                #pragma unroll
                for (int j = 0; j < TN; j++) acc[i][j] += a[i] * b[j];
        }
        __syncthreads();
    }
    #pragma unroll
    for (int i = 0; i < TM; i++) {
        int r = row0 + ty * TM + i;
        float sc = rowdiv ? 1.0f / (rowdiv[r] + 1e-6f) : 1.0f;
        #pragma unroll
        for (int j = 0; j < TN; j++)
            C[(size_t)r * Nc + col0 + tx * TN + j] = acc[i][j] * sc;
    }
}

// ---------------- top-10 per row, lax.top_k tie semantics ----------------
__device__ __forceinline__ unsigned ford(float f) {
    unsigned u = __float_as_uint(f);
    return (u & 0x80000000u) ? ~u : (u | 0x80000000u);
}

__global__ void k_topk(const float* __restrict__ sim) {
    __shared__ unsigned long long keys[N_];   // 32 KB
    __shared__ unsigned long long wmax[8];
    int row = blockIdx.x;
    int tid = threadIdx.x;  // 256
    for (int j = tid; j < N_; j += 256) {
        float v = sim[(size_t)row * N_ + j];
        keys[j] = ((unsigned long long)ford(v) << 32) | (unsigned)(N_ - 1 - j);
    }
    __syncthreads();
    for (int p = 0; p < TOPK_; p++) {
        unsigned long long best = 0ull;
        for (int j = tid; j < N_; j += 256) {
            unsigned long long k = keys[j];
            best = (k > best) ? k : best;
        }
        #pragma unroll
        for (int o = 16; o; o >>= 1) {
            unsigned long long v = __shfl_xor_sync(0xffffffffu, best, o);
            best = (v > best) ? v : best;
        }
        if ((tid & 31) == 0) wmax[tid >> 5] = best;
        __syncthreads();
        if (tid < 32) {
            unsigned long long b2 = (tid < 8) ? wmax[tid] : 0ull;
            #pragma unroll
            for (int o = 4; o; o >>= 1) {
                unsigned long long v = __shfl_xor_sync(0xffffffffu, b2, o);
                b2 = (v > b2) ? v : b2;
            }
            if (tid == 0) {
                int idx = (N_ - 1) - (int)(b2 & 0xffffffffull);
                g_topk[row * TOPK_ + p] = idx;
                keys[idx] = 0ull;
            }
        }
        __syncthreads();
    }
}

// ---------------- sparse A*V via bitmask; one row per block, C_ threads ----------------
__global__ void k_spmm(const unsigned* __restrict__ bits, const float* __restrict__ V,
                       float* __restrict__ out) {
    __shared__ unsigned w[WPR];
    int row = blockIdx.x, tid = threadIdx.x;
    w[tid] = bits[row * WPR + tid];
    __syncthreads();
    float acc = 0.f;
    for (int wi = 0; wi < WPR; wi++) {
        unsigned b = w[wi];
        while (b) {
            int t = __ffs(b) - 1;
            b &= b - 1;
            acc += V[(size_t)((wi << 5) + t) * C_ + tid];
        }
    }
    out[(size_t)row * C_ + tid] = acc;
}

__global__ void k_agg(const float* __restrict__ x, const float* __restrict__ alpha) {
    int i = blockIdx.x * blockDim.x + threadIdx.x;
    if (i >= N_ * C_) return;
    float a0 = __ldg(&alpha[0]), a1 = __ldg(&alpha[1]), a2 = __ldg(&alpha[2]);
    g_agg[i] = a0 * x[i] + a1 * g_Ax[i] + a2 * g_A2x[i];
}

// ---------------- JAX threefry2x32 (key = [0,42]), mask = MSB(bits)==0 ----------------
__device__ __forceinline__ void threefry(unsigned c0, unsigned c1, unsigned& o0, unsigned& o1) {
    const unsigned k0 = 0u, k1 = 42u, k2 = 0u ^ 42u ^ 0x1BD11BDAu;
    unsigned x0 = c0 + k0, x1 = c1 + k1;
    #define TF_R(r) { x0 += x1; x1 = __funnelshift_l(x1, x1, (r)); x1 ^= x0; }
    TF_R(13) TF_R(15) TF_R(26) TF_R(6)   x0 += k1; x1 += k2 + 1u;
    TF_R(17) TF_R(29) TF_R(16) TF_R(24)  x0 += k2; x1 += k0 + 2u;
    TF_R(13) TF_R(15) TF_R(26) TF_R(6)   x0 += k0; x1 += k1 + 3u;
    TF_R(17) TF_R(29) TF_R(16) TF_R(24)  x0 += k1; x1 += k2 + 4u;
    TF_R(13) TF_R(15) TF_R(26) TF_R(6)   x0 += k2; x1 += k0 + 5u;
    #undef TF_R
    o0 = x0; o1 = x1;
}

__global__ void k_threefry_mask() {
    int t = blockIdx.x * blockDim.x + threadIdx.x;   // 0 .. HALF_-1
    unsigned o0, o1;
    threefry((unsigned)t, (unsigned)t + (unsigned)HALF_, o0, o1);
    unsigned m0 = __ballot_sync(0xffffffffu, !(o0 >> 31));
    unsigned m1 = __ballot_sync(0xffffffffu, !(o1 >> 31));
    int lane = threadIdx.x & 31;
    int wbase = t >> 5;                              // same for whole warp
    if (lane == 0)      g_Mbits[wbase] = m0;
    else if (lane == 1) g_Mbits[(HALF_ >> 5) + wbase] = m1;
}

__global__ void k_or_topk() {
    int i = blockIdx.x * blockDim.x + threadIdx.x;
    if (i >= N_ * TOPK_) return;
    int row = i / TOPK_;
    int j = g_topk[i];
    atomicOr(&g_Mbits[row * WPR + (j >> 5)], 1u << (j & 31));
}

__global__ void k_deg() {
    int g    = blockIdx.x * blockDim.x + threadIdx.x;
    int row  = g >> 5;
    int lane = g & 31;
    if (row >= N_) return;
    int cnt = 0;
    #pragma unroll
    for (int i = 0; i < 4; i++) cnt += __popc(g_Mbits[row * WPR + lane + 32 * i]);
    #pragma unroll
    for (int o = 16; o; o >>= 1) cnt += __shfl_xor_sync(0xffffffffu, cnt, o);
    if (lane == 0) g_deg[row] = (float)cnt;
}

__global__ void k_mask_dense() {
    int i = blockIdx.x * blockDim.x + threadIdx.x;   // N_*N_ threads
    unsigned w = g_Mbits[i >> 5];
    g_big[(size_t)i] = (float)((w >> (i & 31)) & 1u);
}

// ---------------- MLP ----------------
__global__ void k_mlp1(const float* __restrict__ x, const float* __restrict__ W,
                       const float* __restrict__ bias) {
    __shared__ float s[16 * 256];
    int r0 = blockIdx.x * 16, tid = threadIdx.x;  // 128 threads
    for (int i = tid; i < 16 * 128; i += 128) {
        int r = i >> 7, c = i & 127;
        s[r * 256 + c]       = x[(size_t)(r0 + r) * 128 + c];
        s[r * 256 + 128 + c] = g_fused[(size_t)(r0 + r) * 128 + c];
    }
    __syncthreads();
    float acc[16];
    float bb = bias[tid];
    #pragma unroll
    for (int r = 0; r < 16; r++) acc[r] = bb;
    for (int k = 0; k < 256; k++) {
        float w = W[k * 128 + tid];
        #pragma unroll
        for (int r = 0; r < 16; r++) acc[r] += s[r * 256 + k] * w;
    }
    #pragma unroll
    for (int r = 0; r < 16; r++) g_h1[(size_t)(r0 + r) * 128 + tid] = acc[r];
}

template<int K, int NCOL, bool RELU>
__global__ void k_mlp(const float* __restrict__ in, const float* __restrict__ W,
                      const float* __restrict__ bias, float* __restrict__ out) {
    __shared__ float s[16 * K];
    int r0 = blockIdx.x * 16, tid = threadIdx.x;  // NCOL threads
    for (int i = tid; i < 16 * K; i += NCOL) s[i] = in[(size_t)r0 * K + i];
    __syncthreads();
    float acc[16];
    float bb = bias[tid];
    #pragma unroll
    for (int r = 0; r < 16; r++) acc[r] = bb;
    for (int k = 0; k < K; k++) {
        float w = W[k * NCOL + tid];
        #pragma unroll
        for (int r = 0; r < 16; r++) acc[r] += s[r * K + k] * w;
    }
    #pragma unroll
    for (int r = 0; r < 16; r++) {
        float v = acc[r];
        if (RELU) v = fmaxf(v, 0.f);
        out[(size_t)(r0 + r) * NCOL + tid] = v;
    }
}

__global__ void k_logsoftmax(float* __restrict__ out) {
    int g    = blockIdx.x * blockDim.x + threadIdx.x;
    int row  = g >> 5;
    int lane = g & 31;
    if (row >= N_) return;
    float v0 = out[(size_t)row * O_ + lane];
    float v1 = out[(size_t)row * O_ + 32 + lane];
    float m = fmaxf(v0, v1);
    #pragma unroll
    for (int o = 16; o; o >>= 1) m = fmaxf(m, __shfl_xor_sync(0xffffffffu, m, o));
    float s = expf(v0 - m) + expf(v1 - m);
    #pragma unroll
    for (int o = 16; o; o >>= 1) s += __shfl_xor_sync(0xffffffffu, s, o);
    float l = m + logf(s);
    out[(size_t)row * O_ + lane]      = v0 - l;
    out[(size_t)row * O_ + 32 + lane] = v1 - l;
}

// ---------------- launch ----------------
extern "C" void kernel_launch(void* const* d_in, const int* in_sizes, int n_in,
                              void* d_out, int out_size) {
    (void)in_sizes; (void)n_in; (void)out_size;
    const float* x     = (const float*)d_in[0];
    const int*   ei    = (const int*)d_in[1];     // int32! (JAX x64 disabled)
    const float* alpha = (const float*)d_in[2];
    const float* fW    = (const float*)d_in[3];
    const float* fb    = (const float*)d_in[4];
    const float* l0W   = (const float*)d_in[5];
    const float* l0b   = (const float*)d_in[6];
    const float* l1W   = (const float*)d_in[7];
    const float* l1b   = (const float*)d_in[8];
    float*       out   = (float*)d_out;

    void *p_big, *p_xn, *p_xnT, *p_agg, *p_fused, *p_h1, *p_h2, *p_deg, *p_Abits, *p_Ax, *p_A2x;
    cudaGetSymbolAddress(&p_big,   g_big);
    cudaGetSymbolAddress(&p_xn,    g_xn);
    cudaGetSymbolAddress(&p_xnT,   g_xnT);
    cudaGetSymbolAddress(&p_agg,   g_agg);
    cudaGetSymbolAddress(&p_fused, g_fused);
    cudaGetSymbolAddress(&p_h1,    g_h1);
    cudaGetSymbolAddress(&p_h2,    g_h2);
    cudaGetSymbolAddress(&p_deg,   g_deg);
    cudaGetSymbolAddress(&p_Abits, g_Abits);
    cudaGetSymbolAddress(&p_Ax,    g_Ax);
    cudaGetSymbolAddress(&p_A2x,   g_A2x);

    // 1. adjacency bitmask
    k_clear_bits<<<(N_ * WPR + 255) / 256, 256>>>();
    k_scatter_edges<<<E_ / 256, 256>>>(ei);

    // 2. cosine sim + topk
    k_rownorm<<<N_ * 32 / 128, 128>>>(x);
    k_transpose<<<dim3(C_ / 32, N_ / 32), dim3(32, 8)>>>((const float*)p_xn, (float*)p_xnT);
    k_gemm<64, 64, 16, 4, 4><<<dim3(N_ / 64, N_ / 64), 256>>>(
        (const float*)p_xn, (const float*)p_xnT, (float*)p_big, N_, N_, C_, nullptr);
    k_topk<<<N_, 256>>>((const float*)p_big);

    // 3. hop features + alpha aggregate
    k_spmm<<<N_, C_>>>((const unsigned*)p_Abits, x, (float*)p_Ax);
    k_spmm<<<N_, C_>>>((const unsigned*)p_Abits, (const float*)p_Ax, (float*)p_A2x);
    k_agg<<<(N_ * C_ + 255) / 256, 256>>>(x, alpha);

    // 4. threefry keep-mask, force topk bits, degree, dense materialize
    k_threefry_mask<<<HALF_ / 256, 256>>>();
    k_or_topk<<<(N_ * TOPK_ + 255) / 256, 256>>>();
    k_deg<<<N_ * 32 / 256, 256>>>();
    k_mask_dense<<<(N_ * N_) / 256, 256>>>();

    // 5. fused = (Mf @ agg) / (deg + 1e-6)
    k_gemm<32, 64, 16, 2, 4><<<dim3(C_ / 64, N_ / 32), 256>>>(
        (const float*)p_big, (const float*)p_agg, (float*)p_fused, N_, C_, N_,
        (const float*)p_deg);

    // 6. MLP + log_softmax
    k_mlp1<<<N_ / 16, 128>>>(x, fW, fb);
    k_mlp<128, 128, true ><<<N_ / 16, 128>>>((const float*)p_h1, l0W, l0b, (float*)p_h2);
    k_mlp<128, 64,  false><<<N_ / 16, 64 >>>((const float*)p_h2, l1W, l1b, out);
    k_logsoftmax<<<N_ * 32 / 128, 128>>>(out);
}

// round 4
// speedup vs baseline: 2.3659x; 2.3659x over previous
#include <cuda_runtime.h>
#include <cuda_bf16.h>
#include <mma.h>
using namespace nvcuda;

#define N_    4096
#define C_    128
#define H_    128
#define O_    64
#define E_    65536
#define WPR   128                 // 32-bit words per mask row (4096/32)
#define HALF_ 8388608             // N*N/2 for threefry pairing
#define TOPK_ 10

// ---------------- scratch (static device globals; no allocation) ----------------
static __device__ unsigned       g_Abits[N_ * WPR];          // 2 MB adjacency bitmask
static __device__ unsigned       g_Mbits[N_ * WPR];          // 2 MB keep-mask bitmask
static __device__ float          g_big[(size_t)N_ * N_];     // 64 MB: sim (fp32)
static __device__ __nv_bfloat16  g_Mbf[(size_t)N_ * N_];     // 32 MB: dense mask bf16
static __device__ __nv_bfloat16  g_xnb[N_ * C_];             // xn in bf16
static __device__ __nv_bfloat16  g_aggT[(size_t)C_ * N_];    // agg^T bf16 [C][N]
static __device__ float          g_Ax [N_ * C_];
static __device__ float          g_A2x[N_ * C_];
static __device__ float          g_fused[N_ * C_];           // raw Mf@agg (pre deg-div)
static __device__ float          g_h1[N_ * H_];
static __device__ float          g_h2[N_ * H_];
static __device__ int            g_topk[N_ * TOPK_];
static __device__ float          g_deg[N_];

// ---------------- adjacency ----------------
__global__ void k_clear_bits() {
    int i = blockIdx.x * blockDim.x + threadIdx.x;
    if (i < N_ * WPR) g_Abits[i] = 0u;
}

// edge_index is int32 (JAX x64 disabled downgrades int64 -> int32), layout [2, E]
__global__ void k_scatter_edges(const int* __restrict__ ei) {
    int i = blockIdx.x * blockDim.x + threadIdx.x;
    if (i >= E_) return;
    int s = ei[i];
    int d = ei[E_ + i];
    atomicOr(&g_Abits[s * WPR + (d >> 5)], 1u << (d & 31));
}

// ---------------- xn = x / (||x|| + 1e-8), stored bf16; one warp per row ----------------
__global__ void k_rownorm(const float* __restrict__ x) {
    int g    = blockIdx.x * blockDim.x + threadIdx.x;
    int row  = g >> 5;
    int lane = g & 31;
    if (row >= N_) return;
    const float4* xr = reinterpret_cast<const float4*>(x + (size_t)row * C_);
    float4 v = xr[lane];
    float s = v.x * v.x + v.y * v.y + v.z * v.z + v.w * v.w;
    #pragma unroll
    for (int o = 16; o; o >>= 1) s += __shfl_xor_sync(0xffffffffu, s, o);
    float inv = 1.0f / (sqrtf(s) + 1e-8f);
    __nv_bfloat162 p0 = __floats2bfloat162_rn(v.x * inv, v.y * inv);
    __nv_bfloat162 p1 = __floats2bfloat162_rn(v.z * inv, v.w * inv);
    __nv_bfloat162* dst = reinterpret_cast<__nv_bfloat162*>(g_xnb + (size_t)row * C_ + lane * 4);
    dst[0] = p0;
    dst[1] = p1;
}

// ---------------- GEMM1: sim = xnb @ xnb^T  (bf16 wmma, fp32 out) ----------------
// block = 256 (8 warps, 2x4), tile 128x128, K = 128 in one shot.
#define G1PAD 16
__global__ void __launch_bounds__(256, 2) k_gemm1_wmma() {
    __shared__ __nv_bfloat16 As[128][128 + G1PAD];
    __shared__ __nv_bfloat16 Bs[128][128 + G1PAD];
    int tid = threadIdx.x;
    int m0 = blockIdx.y * 128, n0 = blockIdx.x * 128;

    // load 128x128 bf16 tiles (16B chunks)
    #pragma unroll
    for (int it = 0; it < 8; it++) {
        int chunk = tid + 256 * it;         // 0..2047
        int r = chunk >> 4, c8 = chunk & 15;
        *reinterpret_cast<uint4*>(&As[r][c8 * 8]) =
            *reinterpret_cast<const uint4*>(g_xnb + (size_t)(m0 + r) * C_ + c8 * 8);
        *reinterpret_cast<uint4*>(&Bs[r][c8 * 8]) =
            *reinterpret_cast<const uint4*>(g_xnb + (size_t)(n0 + r) * C_ + c8 * 8);
    }
    __syncthreads();

    int w = tid >> 5;
    int wm = w >> 2, wn = w & 3;            // warp tile 64x32
    wmma::fragment<wmma::accumulator, 16, 16, 16, float> c[4][2];
    #pragma unroll
    for (int i = 0; i < 4; i++)
        #pragma unroll
        for (int j = 0; j < 2; j++) wmma::fill_fragment(c[i][j], 0.0f);

    #pragma unroll
    for (int kk = 0; kk < 8; kk++) {
        wmma::fragment<wmma::matrix_a, 16, 16, 16, __nv_bfloat16, wmma::row_major> a[4];
        wmma::fragment<wmma::matrix_b, 16, 16, 16, __nv_bfloat16, wmma::col_major> b[2];
        #pragma unroll
        for (int i = 0; i < 4; i++)
            wmma::load_matrix_sync(a[i], &As[wm * 64 + i * 16][kk * 16], 128 + G1PAD);
        #pragma unroll
        for (int j = 0; j < 2; j++)
            wmma::load_matrix_sync(b[j], &Bs[wn * 32 + j * 16][kk * 16], 128 + G1PAD);
        #pragma unroll
        for (int i = 0; i < 4; i++)
            #pragma unroll
            for (int j = 0; j < 2; j++) wmma::mma_sync(c[i][j], a[i], b[j], c[i][j]);
    }
    #pragma unroll
    for (int i = 0; i < 4; i++)
        #pragma unroll
        for (int j = 0; j < 2; j++)
            wmma::store_matrix_sync(
                g_big + (size_t)(m0 + wm * 64 + i * 16) * N_ + n0 + wn * 32 + j * 16,
                c[i][j], N_, wmma::mem_row_major);
}

// ---------------- top-10 per row, lax.top_k tie semantics ----------------
__device__ __forceinline__ unsigned ford(float f) {
    unsigned u = __float_as_uint(f);
    return (u & 0x80000000u) ? ~u : (u | 0x80000000u);
}

__global__ void k_topk(const float* __restrict__ sim) {
    __shared__ unsigned long long keys[N_];   // 32 KB
    __shared__ unsigned long long wmax[8];
    int row = blockIdx.x;
    int tid = threadIdx.x;  // 256
    for (int j = tid; j < N_; j += 256) {
        float v = sim[(size_t)row * N_ + j];
        keys[j] = ((unsigned long long)ford(v) << 32) | (unsigned)(N_ - 1 - j);
    }
    __syncthreads();
    for (int p = 0; p < TOPK_; p++) {
        unsigned long long best = 0ull;
        for (int j = tid; j < N_; j += 256) {
            unsigned long long k = keys[j];
            best = (k > best) ? k : best;
        }
        #pragma unroll
        for (int o = 16; o; o >>= 1) {
            unsigned long long v = __shfl_xor_sync(0xffffffffu, best, o);
            best = (v > best) ? v : best;
        }
        if ((tid & 31) == 0) wmax[tid >> 5] = best;
        __syncthreads();
        if (tid < 32) {
            unsigned long long b2 = (tid < 8) ? wmax[tid] : 0ull;
            #pragma unroll
            for (int o = 4; o; o >>= 1) {
                unsigned long long v = __shfl_xor_sync(0xffffffffu, b2, o);
                b2 = (v > b2) ? v : b2;
            }
            if (tid == 0) {
                int idx = (N_ - 1) - (int)(b2 & 0xffffffffull);
                g_topk[row * TOPK_ + p] = idx;
                keys[idx] = 0ull;
            }
        }
        __syncthreads();
    }
}

// ---------------- sparse A*V via bitmask; one row per block, C_ threads ----------------
__global__ void k_spmm(const unsigned* __restrict__ bits, const float* __restrict__ V,
                       float* __restrict__ out) {
    __shared__ unsigned w[WPR];
    int row = blockIdx.x, tid = threadIdx.x;
    w[tid] = bits[row * WPR + tid];
    __syncthreads();
    float acc = 0.f;
    for (int wi = 0; wi < WPR; wi++) {
        unsigned b = w[wi];
        while (b) {
            int t = __ffs(b) - 1;
            b &= b - 1;
            acc += V[(size_t)((wi << 5) + t) * C_ + tid];
        }
    }
    out[(size_t)row * C_ + tid] = acc;
}

// ---------------- aggT[c][n] = bf16(a0*x + a1*Ax + a2*A2x)  (fused transpose) ---------
__global__ void k_aggT(const float* __restrict__ x, const float* __restrict__ alpha) {
    __shared__ float t[32][33];
    int c0 = blockIdx.x * 32, r0 = blockIdx.y * 32;
    int tx = threadIdx.x, ty = threadIdx.y; // 32 x 8
    float a0 = __ldg(&alpha[0]), a1 = __ldg(&alpha[1]), a2 = __ldg(&alpha[2]);
    #pragma unroll
    for (int i = 0; i < 4; i++) {
        size_t idx = (size_t)(r0 + ty + 8 * i) * C_ + c0 + tx;
        t[ty + 8 * i][tx] = a0 * x[idx] + a1 * g_Ax[idx] + a2 * g_A2x[idx];
    }
    __syncthreads();
    #pragma unroll
    for (int i = 0; i < 4; i++)
        g_aggT[(size_t)(c0 + ty + 8 * i) * N_ + r0 + tx] = __float2bfloat16(t[tx][ty + 8 * i]);
}

// ---------------- JAX threefry2x32 (key = [0,42]), mask = MSB(bits)==0 ----------------
__device__ __forceinline__ void threefry(unsigned c0, unsigned c1, unsigned& o0, unsigned& o1) {
    const unsigned k0 = 0u, k1 = 42u, k2 = 0u ^ 42u ^ 0x1BD11BDAu;
    unsigned x0 = c0 + k0, x1 = c1 + k1;
    #define TF_R(r) { x0 += x1; x1 = __funnelshift_l(x1, x1, (r)); x1 ^= x0; }
    TF_R(13) TF_R(15) TF_R(26) TF_R(6)   x0 += k1; x1 += k2 + 1u;
    TF_R(17) TF_R(29) TF_R(16) TF_R(24)  x0 += k2; x1 += k0 + 2u;
    TF_R(13) TF_R(15) TF_R(26) TF_R(6)   x0 += k0; x1 += k1 + 3u;
    TF_R(17) TF_R(29) TF_R(16) TF_R(24)  x0 += k1; x1 += k2 + 4u;
    TF_R(13) TF_R(15) TF_R(26) TF_R(6)   x0 += k2; x1 += k0 + 5u;
    #undef TF_R
    o0 = x0; o1 = x1;
}

__global__ void k_threefry_mask() {
    int t = blockIdx.x * blockDim.x + threadIdx.x;   // 0 .. HALF_-1
    unsigned o0, o1;
    threefry((unsigned)t, (unsigned)t + (unsigned)HALF_, o0, o1);
    unsigned m0 = __ballot_sync(0xffffffffu, !(o0 >> 31));
    unsigned m1 = __ballot_sync(0xffffffffu, !(o1 >> 31));
    int lane = threadIdx.x & 31;
    int wbase = t >> 5;                              // same for whole warp
    if (lane == 0)      g_Mbits[wbase] = m0;
    else if (lane == 1) g_Mbits[(HALF_ >> 5) + wbase] = m1;
}

__global__ void k_or_topk() {
    int i = blockIdx.x * blockDim.x + threadIdx.x;
    if (i >= N_ * TOPK_) return;
    int row = i / TOPK_;
    int j = g_topk[i];
    atomicOr(&g_Mbits[row * WPR + (j >> 5)], 1u << (j & 31));
}

__global__ void k_deg() {
    int g    = blockIdx.x * blockDim.x + threadIdx.x;
    int row  = g >> 5;
    int lane = g & 31;
    if (row >= N_) return;
    int cnt = 0;
    #pragma unroll
    for (int i = 0; i < 4; i++) cnt += __popc(g_Mbits[row * WPR + lane + 32 * i]);
    #pragma unroll
    for (int o = 16; o; o >>= 1) cnt += __shfl_xor_sync(0xffffffffu, cnt, o);
    if (lane == 0) g_deg[row] = (float)cnt;
}

// dense bf16 mask from bits: one 32-bit word -> 32 bf16 (64B) per thread
__global__ void k_mask_bf16() {
    int t = blockIdx.x * blockDim.x + threadIdx.x;   // 0 .. N_*WPR-1
    unsigned w = g_Mbits[t];
    __nv_bfloat16* dst = g_Mbf + (size_t)t * 32;
    #pragma unroll
    for (int gq = 0; gq < 4; gq++) {
        uint4 v;
        unsigned b = w >> (gq * 8);
        v.x = ((b      & 1u) ? 0x3F80u : 0u) | (((b >> 1) & 1u) ? 0x3F800000u : 0u);
        v.y = (((b >> 2) & 1u) ? 0x3F80u : 0u) | (((b >> 3) & 1u) ? 0x3F800000u : 0u);
        v.z = (((b >> 4) & 1u) ? 0x3F80u : 0u) | (((b >> 5) & 1u) ? 0x3F800000u : 0u);
        v.w = (((b >> 6) & 1u) ? 0x3F80u : 0u) | (((b >> 7) & 1u) ? 0x3F800000u : 0u);
        reinterpret_cast<uint4*>(dst)[gq] = v;
    }
}

// ---------------- GEMM2: fused_raw = Mbf[4096,4096] @ aggT^T  (bf16 wmma) -------------
// grid 32 (M blocks), block 256 (8 warps 2x4), N=128 in-block, BK=64.
#define G2PAD 16
__global__ void __launch_bounds__(256, 2) k_gemm2_wmma() {
    __shared__ __nv_bfloat16 As[128][64 + G2PAD];
    __shared__ __nv_bfloat16 Bs[128][64 + G2PAD];
    int tid = threadIdx.x;
    int m0 = blockIdx.x * 128;
    int w = tid >> 5;
    int wm = w >> 2, wn = w & 3;            // warp tile 64x32

    wmma::fragment<wmma::accumulator, 16, 16, 16, float> c[4][2];
    #pragma unroll
    for (int i = 0; i < 4; i++)
        #pragma unroll
        for (int j = 0; j < 2; j++) wmma::fill_fragment(c[i][j], 0.0f);

    for (int k0 = 0; k0 < N_; k0 += 64) {
        #pragma unroll
        for (int it = 0; it < 4; it++) {
            int chunk = tid + 256 * it;     // 0..1023
            int r = chunk >> 3, c8 = chunk & 7;
            *reinterpret_cast<uint4*>(&As[r][c8 * 8]) =
                *reinterpret_cast<const uint4*>(g_Mbf + (size_t)(m0 + r) * N_ + k0 + c8 * 8);
            *reinterpret_cast<uint4*>(&Bs[r][c8 * 8]) =
                *reinterpret_cast<const uint4*>(g_aggT + (size_t)r * N_ + k0 + c8 * 8);
        }
        __syncthreads();
        #pragma unroll
        for (int kk = 0; kk < 4; kk++) {
            wmma::fragment<wmma::matrix_a, 16, 16, 16, __nv_bfloat16, wmma::row_major> a[4];
            wmma::fragment<wmma::matrix_b, 16, 16, 16, __nv_bfloat16, wmma::col_major> b[2];
            #pragma unroll
            for (int i = 0; i < 4; i++)
                wmma::load_matrix_sync(a[i], &As[wm * 64 + i * 16][kk * 16], 64 + G2PAD);
            #pragma unroll
            for (int j = 0; j < 2; j++)
                wmma::load_matrix_sync(b[j], &Bs[wn * 32 + j * 16][kk * 16], 64 + G2PAD);
            #pragma unroll
            for (int i = 0; i < 4; i++)
                #pragma unroll
                for (int j = 0; j < 2; j++) wmma::mma_sync(c[i][j], a[i], b[j], c[i][j]);
        }
        __syncthreads();
    }
    #pragma unroll
    for (int i = 0; i < 4; i++)
        #pragma unroll
        for (int j = 0; j < 2; j++)
            wmma::store_matrix_sync(
                g_fused + (size_t)(m0 + wm * 64 + i * 16) * C_ + wn * 32 + j * 16,
                c[i][j], C_, wmma::mem_row_major);
}

// ---------------- MLP (deg division folded into fused load) ----------------
__global__ void k_mlp1(const float* __restrict__ x, const float* __restrict__ W,
                       const float* __restrict__ bias) {
    __shared__ float s[16 * 256];
    int r0 = blockIdx.x * 16, tid = threadIdx.x;  // 128 threads
    for (int i = tid; i < 16 * 128; i += 128) {
        int r = i >> 7, c = i & 127;
        float invd = 1.0f / (g_deg[r0 + r] + 1e-6f);
        s[r * 256 + c]       = x[(size_t)(r0 + r) * 128 + c];
        s[r * 256 + 128 + c] = g_fused[(size_t)(r0 + r) * 128 + c] * invd;
    }
    __syncthreads();
    float acc[16];
    float bb = bias[tid];
    #pragma unroll
    for (int r = 0; r < 16; r++) acc[r] = bb;
    for (int k = 0; k < 256; k++) {
        float w = W[k * 128 + tid];
        #pragma unroll
        for (int r = 0; r < 16; r++) acc[r] += s[r * 256 + k] * w;
    }
    #pragma unroll
    for (int r = 0; r < 16; r++) g_h1[(size_t)(r0 + r) * 128 + tid] = acc[r];
}

template<int K, int NCOL, bool RELU>
__global__ void k_mlp(const float* __restrict__ in, const float* __restrict__ W,
                      const float* __restrict__ bias, float* __restrict__ out) {
    __shared__ float s[16 * K];
    int r0 = blockIdx.x * 16, tid = threadIdx.x;  // NCOL threads
    for (int i = tid; i < 16 * K; i += NCOL) s[i] = in[(size_t)r0 * K + i];
    __syncthreads();
    float acc[16];
    float bb = bias[tid];
    #pragma unroll
    for (int r = 0; r < 16; r++) acc[r] = bb;
    for (int k = 0; k < K; k++) {
        float w = W[k * NCOL + tid];
        #pragma unroll
        for (int r = 0; r < 16; r++) acc[r] += s[r * K + k] * w;
    }
    #pragma unroll
    for (int r = 0; r < 16; r++) {
        float v = acc[r];
        if (RELU) v = fmaxf(v, 0.f);
        out[(size_t)(r0 + r) * NCOL + tid] = v;
    }
}

__global__ void k_logsoftmax(float* __restrict__ out) {
    int g    = blockIdx.x * blockDim.x + threadIdx.x;
    int row  = g >> 5;
    int lane = g & 31;
    if (row >= N_) return;
    float v0 = out[(size_t)row * O_ + lane];
    float v1 = out[(size_t)row * O_ + 32 + lane];
    float m = fmaxf(v0, v1);
    #pragma unroll
    for (int o = 16; o; o >>= 1) m = fmaxf(m, __shfl_xor_sync(0xffffffffu, m, o));
    float s = expf(v0 - m) + expf(v1 - m);
    #pragma unroll
    for (int o = 16; o; o >>= 1) s += __shfl_xor_sync(0xffffffffu, s, o);
    float l = m + logf(s);
    out[(size_t)row * O_ + lane]      = v0 - l;
    out[(size_t)row * O_ + 32 + lane] = v1 - l;
}

// ---------------- launch ----------------
extern "C" void kernel_launch(void* const* d_in, const int* in_sizes, int n_in,
                              void* d_out, int out_size) {
    (void)in_sizes; (void)n_in; (void)out_size;
    const float* x     = (const float*)d_in[0];
    const int*   ei    = (const int*)d_in[1];     // int32 (JAX x64 disabled)
    const float* alpha = (const float*)d_in[2];
    const float* fW    = (const float*)d_in[3];
    const float* fb    = (const float*)d_in[4];
    const float* l0W   = (const float*)d_in[5];
    const float* l0b   = (const float*)d_in[6];
    const float* l1W   = (const float*)d_in[7];
    const float* l1b   = (const float*)d_in[8];
    float*       out   = (float*)d_out;

    void *p_big, *p_h1, *p_h2, *p_Abits, *p_Ax, *p_A2x;
    cudaGetSymbolAddress(&p_big,   g_big);
    cudaGetSymbolAddress(&p_h1,    g_h1);
    cudaGetSymbolAddress(&p_h2,    g_h2);
    cudaGetSymbolAddress(&p_Abits, g_Abits);
    cudaGetSymbolAddress(&p_Ax,    g_Ax);
    cudaGetSymbolAddress(&p_A2x,   g_A2x);

    // 1. adjacency bitmask
    k_clear_bits<<<(N_ * WPR + 255) / 256, 256>>>();
    k_scatter_edges<<<E_ / 256, 256>>>(ei);

    // 2. cosine sim (bf16 tensor cores) + topk
    k_rownorm<<<N_ * 32 / 128, 128>>>(x);
    k_gemm1_wmma<<<dim3(N_ / 128, N_ / 128), 256>>>();
    k_topk<<<N_, 256>>>((const float*)p_big);

    // 3. hop features + alpha aggregate (transposed, bf16)
    k_spmm<<<N_, C_>>>((const unsigned*)p_Abits, x, (float*)p_Ax);
    k_spmm<<<N_, C_>>>((const unsigned*)p_Abits, (const float*)p_Ax, (float*)p_A2x);
    k_aggT<<<dim3(C_ / 32, N_ / 32), dim3(32, 8)>>>(x, alpha);

    // 4. threefry keep-mask, force topk bits, degree, dense bf16 materialize
    k_threefry_mask<<<HALF_ / 256, 256>>>();
    k_or_topk<<<(N_ * TOPK_ + 255) / 256, 256>>>();
    k_deg<<<N_ * 32 / 256, 256>>>();
    k_mask_bf16<<<N_ * WPR / 256, 256>>>();

    // 5. fused_raw = Mf @ agg (bf16 tensor cores); deg-div folded into k_mlp1
    k_gemm2_wmma<<<N_ / 128, 256>>>();

    // 6. MLP + log_softmax
    k_mlp1<<<N_ / 16, 128>>>(x, fW, fb);
    k_mlp<128, 128, true ><<<N_ / 16, 128>>>((const float*)p_h1, l0W, l0b, (float*)p_h2);
    k_mlp<128, 64,  false><<<N_ / 16, 64 >>>((const float*)p_h2, l1W, l1b, out);
    k_logsoftmax<<<N_ * 32 / 128, 128>>>(out);
}

// round 6
// speedup vs baseline: 3.2947x; 1.3926x over previous
#include <cuda_runtime.h>
#include <cuda_bf16.h>
#include <mma.h>
using namespace nvcuda;

#define N_    4096
#define C_    128
#define H_    128
#define O_    64
#define E_    65536
#define WPR   128                 // 32-bit words per mask row (4096/32)
#define HALF_ 8388608             // N*N/2 for threefry pairing
#define TOPK_ 10
#define KSPLIT 8                  // gemm2 split-K factor

// ---------------- scratch (static device globals; no allocation) ----------------
static __device__ unsigned       g_Abits[N_ * WPR];          // 2 MB adjacency bitmask
static __device__ unsigned       g_Mbits[N_ * WPR];          // 2 MB keep-mask bitmask
static __device__ float          g_big[(size_t)N_ * N_];     // 64 MB: sim; later gemm2 partials
static __device__ __nv_bfloat16  g_Mbf[(size_t)N_ * N_];     // 32 MB: dense mask bf16
static __device__ __nv_bfloat16  g_xnb[N_ * C_];             // xn in bf16
static __device__ __nv_bfloat16  g_aggT[(size_t)C_ * N_];    // agg^T bf16 [C][N]
static __device__ float          g_Ax [N_ * C_];
static __device__ float          g_A2x[N_ * C_];
static __device__ float          g_fused[N_ * C_];           // raw Mf@agg (pre deg-div)
static __device__ float          g_h1[N_ * H_];
static __device__ float          g_h2[N_ * H_];
static __device__ int            g_topk[N_ * TOPK_];
static __device__ float          g_deg[N_];

// ---------------- adjacency ----------------
__global__ void k_clear_bits() {
    int i = blockIdx.x * blockDim.x + threadIdx.x;
    if (i < N_ * WPR) g_Abits[i] = 0u;
}

// edge_index is int32 (JAX x64 disabled downgrades int64 -> int32), layout [2, E]
__global__ void k_scatter_edges(const int* __restrict__ ei) {
    int i = blockIdx.x * blockDim.x + threadIdx.x;
    if (i >= E_) return;
    int s = ei[i];
    int d = ei[E_ + i];
    atomicOr(&g_Abits[s * WPR + (d >> 5)], 1u << (d & 31));
}

// ---------------- xn = x / (||x|| + 1e-8), stored bf16; one warp per row ----------------
__global__ void k_rownorm(const float* __restrict__ x) {
    int g    = blockIdx.x * blockDim.x + threadIdx.x;
    int row  = g >> 5;
    int lane = g & 31;
    if (row >= N_) return;
    const float4* xr = reinterpret_cast<const float4*>(x + (size_t)row * C_);
    float4 v = xr[lane];
    float s = v.x * v.x + v.y * v.y + v.z * v.z + v.w * v.w;
    #pragma unroll
    for (int o = 16; o; o >>= 1) s += __shfl_xor_sync(0xffffffffu, s, o);
    float inv = 1.0f / (sqrtf(s) + 1e-8f);
    __nv_bfloat162 p0 = __floats2bfloat162_rn(v.x * inv, v.y * inv);
    __nv_bfloat162 p1 = __floats2bfloat162_rn(v.z * inv, v.w * inv);
    __nv_bfloat162* dst = reinterpret_cast<__nv_bfloat162*>(g_xnb + (size_t)row * C_ + lane * 4);
    dst[0] = p0;
    dst[1] = p1;
}

// ---------------- GEMM1: sim = xnb @ xnb^T  (bf16 wmma, fp32 out) ----------------
#define G1PAD 16
__global__ void __launch_bounds__(256, 2) k_gemm1_wmma() {
    __shared__ __nv_bfloat16 As[128][128 + G1PAD];
    __shared__ __nv_bfloat16 Bs[128][128 + G1PAD];
    int tid = threadIdx.x;
    int m0 = blockIdx.y * 128, n0 = blockIdx.x * 128;

    #pragma unroll
    for (int it = 0; it < 8; it++) {
        int chunk = tid + 256 * it;         // 0..2047
        int r = chunk >> 4, c8 = chunk & 15;
        *reinterpret_cast<uint4*>(&As[r][c8 * 8]) =
            *reinterpret_cast<const uint4*>(g_xnb + (size_t)(m0 + r) * C_ + c8 * 8);
        *reinterpret_cast<uint4*>(&Bs[r][c8 * 8]) =
            *reinterpret_cast<const uint4*>(g_xnb + (size_t)(n0 + r) * C_ + c8 * 8);
    }
    __syncthreads();

    int w = tid >> 5;
    int wm = w >> 2, wn = w & 3;            // warp tile 64x32
    wmma::fragment<wmma::accumulator, 16, 16, 16, float> c[4][2];
    #pragma unroll
    for (int i = 0; i < 4; i++)
        #pragma unroll
        for (int j = 0; j < 2; j++) wmma::fill_fragment(c[i][j], 0.0f);

    #pragma unroll
    for (int kk = 0; kk < 8; kk++) {
        wmma::fragment<wmma::matrix_a, 16, 16, 16, __nv_bfloat16, wmma::row_major> a[4];
        wmma::fragment<wmma::matrix_b, 16, 16, 16, __nv_bfloat16, wmma::col_major> b[2];
        #pragma unroll
        for (int i = 0; i < 4; i++)
            wmma::load_matrix_sync(a[i], &As[wm * 64 + i * 16][kk * 16], 128 + G1PAD);
        #pragma unroll
        for (int j = 0; j < 2; j++)
            wmma::load_matrix_sync(b[j], &Bs[wn * 32 + j * 16][kk * 16], 128 + G1PAD);
        #pragma unroll
        for (int i = 0; i < 4; i++)
            #pragma unroll
            for (int j = 0; j < 2; j++) wmma::mma_sync(c[i][j], a[i], b[j], c[i][j]);
    }
    #pragma unroll
    for (int i = 0; i < 4; i++)
        #pragma unroll
        for (int j = 0; j < 2; j++)
            wmma::store_matrix_sync(
                g_big + (size_t)(m0 + wm * 64 + i * 16) * N_ + n0 + wn * 32 + j * 16,
                c[i][j], N_, wmma::mem_row_major);
}

// ---------------- top-10 per row (register-resident keys), lax.top_k ties ------------
__device__ __forceinline__ unsigned ford(float f) {
    unsigned u = __float_as_uint(f);
    return (u & 0x80000000u) ? ~u : (u | 0x80000000u);
}

__global__ void __launch_bounds__(256) k_topk(const float* __restrict__ sim) {
    __shared__ unsigned long long wbest[8];
    __shared__ unsigned long long winner;
    int row  = blockIdx.x;
    int tid  = threadIdx.x;          // 256 = 8 warps
    int w    = tid >> 5;
    int lane = tid & 31;

    // warp w owns columns [w*512, (w+1)*512); thread holds 16 keys in registers
    unsigned long long key[16];
    #pragma unroll
    for (int i = 0; i < 16; i++) {
        int j = w * 512 + i * 32 + lane;
        float v = sim[(size_t)row * N_ + j];
        key[i] = ((unsigned long long)ford(v) << 32) | (unsigned)(N_ - 1 - j);
    }

    for (int p = 0; p < TOPK_; p++) {
        unsigned long long m = 0ull;
        #pragma unroll
        for (int i = 0; i < 16; i++) m = (key[i] > m) ? key[i] : m;
        unsigned long long wm = m;
        #pragma unroll
        for (int o = 16; o; o >>= 1) {
            unsigned long long v = __shfl_xor_sync(0xffffffffu, wm, o);
            wm = (v > wm) ? v : wm;
        }
        if (lane == 0) wbest[w] = wm;
        __syncthreads();
        if (tid < 32) {
            unsigned long long b = (tid < 8) ? wbest[tid] : 0ull;
            #pragma unroll
            for (int o = 4; o; o >>= 1) {
                unsigned long long v = __shfl_xor_sync(0xffffffffu, b, o);
                b = (v > b) ? v : b;
            }
            if (tid == 0) {
                winner = b;
                g_topk[row * TOPK_ + p] = (N_ - 1) - (int)(b & 0xffffffffull);
            }
        }
        __syncthreads();
        unsigned long long wn = winner;
        if (m == wn) {   // exactly one thread holds it (index makes keys unique)
            #pragma unroll
            for (int i = 0; i < 16; i++) if (key[i] == wn) key[i] = 0ull;
        }
        __syncthreads();
    }
}

// ---------------- sparse A*V: decode neighbor list, then ILP-4 accumulate ------------
__global__ void __launch_bounds__(128) k_spmm(const unsigned* __restrict__ bits,
                                              const float* __restrict__ V,
                                              float* __restrict__ out) {
    __shared__ unsigned short nbr[N_];   // worst-case full row, 8 KB
    __shared__ int wsum[4];
    int row = blockIdx.x, tid = threadIdx.x;   // 128 threads = 128 words = 128 cols
    int lane = tid & 31, w = tid >> 5;

    unsigned word = bits[row * WPR + tid];
    int cnt = __popc(word);
    int inc = cnt;
    #pragma unroll
    for (int o = 1; o < 32; o <<= 1) {
        int v = __shfl_up_sync(0xffffffffu, inc, o);
        if (lane >= o) inc += v;
    }
    if (lane == 31) wsum[w] = inc;
    __syncthreads();
    int base = 0;
    #pragma unroll
    for (int i = 0; i < 4; i++) if (i < w) base += wsum[i];
    int off = base + inc - cnt;
    unsigned b = word;
    while (b) {
        int t = __ffs(b) - 1;
        b &= b - 1;
        nbr[off++] = (unsigned short)((tid << 5) + t);
    }
    int nn = wsum[0] + wsum[1] + wsum[2] + wsum[3];
    __syncthreads();

    float a0 = 0.f, a1 = 0.f, a2 = 0.f, a3 = 0.f;
    int i = 0;
    for (; i + 4 <= nn; i += 4) {
        int j0 = nbr[i], j1 = nbr[i + 1], j2 = nbr[i + 2], j3 = nbr[i + 3];
        a0 += V[(size_t)j0 * C_ + tid];
        a1 += V[(size_t)j1 * C_ + tid];
        a2 += V[(size_t)j2 * C_ + tid];
        a3 += V[(size_t)j3 * C_ + tid];
    }
    for (; i < nn; i++) a0 += V[(size_t)nbr[i] * C_ + tid];
    out[(size_t)row * C_ + tid] = (a0 + a1) + (a2 + a3);
}

// ---------------- aggT[c][n] = bf16(a0*x + a1*Ax + a2*A2x)  (fused transpose) ---------
__global__ void k_aggT(const float* __restrict__ x, const float* __restrict__ alpha) {
    __shared__ float t[32][33];
    int c0 = blockIdx.x * 32, r0 = blockIdx.y * 32;
    int tx = threadIdx.x, ty = threadIdx.y; // 32 x 8
    float a0 = __ldg(&alpha[0]), a1 = __ldg(&alpha[1]), a2 = __ldg(&alpha[2]);
    #pragma unroll
    for (int i = 0; i < 4; i++) {
        size_t idx = (size_t)(r0 + ty + 8 * i) * C_ + c0 + tx;
        t[ty + 8 * i][tx] = a0 * x[idx] + a1 * g_Ax[idx] + a2 * g_A2x[idx];
    }
    __syncthreads();
    #pragma unroll
    for (int i = 0; i < 4; i++)
        g_aggT[(size_t)(c0 + ty + 8 * i) * N_ + r0 + tx] = __float2bfloat16(t[tx][ty + 8 * i]);
}

// ---------------- JAX threefry2x32 (key = [0,42]), mask = MSB(bits)==0 ----------------
__device__ __forceinline__ void threefry(unsigned c0, unsigned c1, unsigned& o0, unsigned& o1) {
    const unsigned k0 = 0u, k1 = 42u, k2 = 0u ^ 42u ^ 0x1BD11BDAu;
    unsigned x0 = c0 + k0, x1 = c1 + k1;
    #define TF_R(r) { x0 += x1; x1 = __funnelshift_l(x1, x1, (r)); x1 ^= x0; }
    TF_R(13) TF_R(15) TF_R(26) TF_R(6)   x0 += k1; x1 += k2 + 1u;
    TF_R(17) TF_R(29) TF_R(16) TF_R(24)  x0 += k2; x1 += k0 + 2u;
    TF_R(13) TF_R(15) TF_R(26) TF_R(6)   x0 += k0; x1 += k1 + 3u;
    TF_R(17) TF_R(29) TF_R(16) TF_R(24)  x0 += k1; x1 += k2 + 4u;
    TF_R(13) TF_R(15) TF_R(26) TF_R(6)   x0 += k2; x1 += k0 + 5u;
    #undef TF_R
    o0 = x0; o1 = x1;
}

__global__ void k_threefry_mask() {
    int t = blockIdx.x * blockDim.x + threadIdx.x;   // 0 .. HALF_-1
    unsigned o0, o1;
    threefry((unsigned)t, (unsigned)t + (unsigned)HALF_, o0, o1);
    unsigned m0 = __ballot_sync(0xffffffffu, !(o0 >> 31));
    unsigned m1 = __ballot_sync(0xffffffffu, !(o1 >> 31));
    int lane = threadIdx.x & 31;
    int wbase = t >> 5;                              // same for whole warp
    if (lane == 0)      g_Mbits[wbase] = m0;
    else if (lane == 1) g_Mbits[(HALF_ >> 5) + wbase] = m1;
}

__global__ void k_or_topk() {
    int i = blockIdx.x * blockDim.x + threadIdx.x;
    if (i >= N_ * TOPK_) return;
    int row = i / TOPK_;
    int j = g_topk[i];
    atomicOr(&g_Mbits[row * WPR + (j >> 5)], 1u << (j & 31));
}

// fused: dense bf16 mask expansion + row degree (single Mbits read)
__global__ void __launch_bounds__(128) k_mask_deg() {
    __shared__ int wsum[4];
    int row = blockIdx.x, tid = threadIdx.x;   // 128 threads = 128 words
    int lane = tid & 31, w = tid >> 5;
    unsigned wd = g_Mbits[row * WPR + tid];

    __nv_bfloat16* dst = g_Mbf + (size_t)row * N_ + tid * 32;
    #pragma unroll
    for (int gq = 0; gq < 4; gq++) {
        uint4 v;
        unsigned b = wd >> (gq * 8);
        v.x = ((b      & 1u) ? 0x3F80u : 0u) | (((b >> 1) & 1u) ? 0x3F800000u : 0u);
        v.y = (((b >> 2) & 1u) ? 0x3F80u : 0u) | (((b >> 3) & 1u) ? 0x3F800000u : 0u);
        v.z = (((b >> 4) & 1u) ? 0x3F80u : 0u) | (((b >> 5) & 1u) ? 0x3F800000u : 0u);
        v.w = (((b >> 6) & 1u) ? 0x3F80u : 0u) | (((b >> 7) & 1u) ? 0x3F800000u : 0u);
        reinterpret_cast<uint4*>(dst)[gq] = v;
    }
    int c = __popc(wd);
    #pragma unroll
    for (int o = 16; o; o >>= 1) c += __shfl_xor_sync(0xffffffffu, c, o);
    if (lane == 0) wsum[w] = c;
    __syncthreads();
    if (tid == 0) g_deg[row] = (float)(wsum[0] + wsum[1] + wsum[2] + wsum[3]);
}

// ---------------- GEMM2 split-K: partial[s] = Mbf[:, sK:(s+1)K] @ aggT^T chunk --------
// grid (KSPLIT, 32), block 256 (8 warps 2x4). Partials land in g_big (free after topk).
#define G2PAD 16
__global__ void __launch_bounds__(256, 2) k_gemm2_wmma() {
    __shared__ __nv_bfloat16 As[128][64 + G2PAD];
    __shared__ __nv_bfloat16 Bs[128][64 + G2PAD];
    int tid = threadIdx.x;
    int split = blockIdx.x;
    int m0 = blockIdx.y * 128;
    int kbase = split * (N_ / KSPLIT);
    int w = tid >> 5;
    int wm = w >> 2, wn = w & 3;            // warp tile 64x32

    wmma::fragment<wmma::accumulator, 16, 16, 16, float> c[4][2];
    #pragma unroll
    for (int i = 0; i < 4; i++)
        #pragma unroll
        for (int j = 0; j < 2; j++) wmma::fill_fragment(c[i][j], 0.0f);

    for (int k0 = kbase; k0 < kbase + N_ / KSPLIT; k0 += 64) {
        #pragma unroll
        for (int it = 0; it < 4; it++) {
            int chunk = tid + 256 * it;     // 0..1023
            int r = chunk >> 3, c8 = chunk & 7;
            *reinterpret_cast<uint4*>(&As[r][c8 * 8]) =
                *reinterpret_cast<const uint4*>(g_Mbf + (size_t)(m0 + r) * N_ + k0 + c8 * 8);
            *reinterpret_cast<uint4*>(&Bs[r][c8 * 8]) =
                *reinterpret_cast<const uint4*>(g_aggT + (size_t)r * N_ + k0 + c8 * 8);
        }
        __syncthreads();
        #pragma unroll
        for (int kk = 0; kk < 4; kk++) {
            wmma::fragment<wmma::matrix_a, 16, 16, 16, __nv_bfloat16, wmma::row_major> a[4];
            wmma::fragment<wmma::matrix_b, 16, 16, 16, __nv_bfloat16, wmma::col_major> b[2];
            #pragma unroll
            for (int i = 0; i < 4; i++)
                wmma::load_matrix_sync(a[i], &As[wm * 64 + i * 16][kk * 16], 64 + G2PAD);
            #pragma unroll
            for (int j = 0; j < 2; j++)
                wmma::load_matrix_sync(b[j], &Bs[wn * 32 + j * 16][kk * 16], 64 + G2PAD);
            #pragma unroll
            for (int i = 0; i < 4; i++)
                #pragma unroll
                for (int j = 0; j < 2; j++) wmma::mma_sync(c[i][j], a[i], b[j], c[i][j]);
        }
        __syncthreads();
    }
    float* dst = g_big + (size_t)split * (N_ * C_);
    #pragma unroll
    for (int i = 0; i < 4; i++)
        #pragma unroll
        for (int j = 0; j < 2; j++)
            wmma::store_matrix_sync(
                dst + (size_t)(m0 + wm * 64 + i * 16) * C_ + wn * 32 + j * 16,
                c[i][j], C_, wmma::mem_row_major);
}

// deterministic split-K reduce
__global__ void k_reduce_splits() {
    int i = blockIdx.x * blockDim.x + threadIdx.x;
    if (i >= N_ * C_) return;
    float s = 0.f;
    #pragma unroll
    for (int k = 0; k < KSPLIT; k++) s += g_big[(size_t)k * (N_ * C_) + i];
    g_fused[i] = s;
}

// ---------------- MLP (deg division folded into fused load) ----------------
__global__ void k_mlp1(const float* __restrict__ x, const float* __restrict__ W,
                       const float* __restrict__ bias) {
    __shared__ float s[16 * 256];
    int r0 = blockIdx.x * 16, tid = threadIdx.x;  // 128 threads
    for (int i = tid; i < 16 * 128; i += 128) {
        int r = i >> 7, c = i & 127;
        float invd = 1.0f / (g_deg[r0 + r] + 1e-6f);
        s[r * 256 + c]       = x[(size_t)(r0 + r) * 128 + c];
        s[r * 256 + 128 + c] = g_fused[(size_t)(r0 + r) * 128 + c] * invd;
    }
    __syncthreads();
    float acc[16];
    float bb = bias[tid];
    #pragma unroll
    for (int r = 0; r < 16; r++) acc[r] = bb;
    for (int k = 0; k < 256; k++) {
        float w = W[k * 128 + tid];
        #pragma unroll
        for (int r = 0; r < 16; r++) acc[r] += s[r * 256 + k] * w;
    }
    #pragma unroll
    for (int r = 0; r < 16; r++) g_h1[(size_t)(r0 + r) * 128 + tid] = acc[r];
}

template<int K, int NCOL, bool RELU>
__global__ void k_mlp(const float* __restrict__ in, const float* __restrict__ W,
                      const float* __restrict__ bias, float* __restrict__ out) {
    __shared__ float s[16 * K];
    int r0 = blockIdx.x * 16, tid = threadIdx.x;  // NCOL threads
    for (int i = tid; i < 16 * K; i += NCOL) s[i] = in[(size_t)r0 * K + i];
    __syncthreads();
    float acc[16];
    float bb = bias[tid];
    #pragma unroll
    for (int r = 0; r < 16; r++) acc[r] = bb;
    for (int k = 0; k < K; k++) {
        float w = W[k * NCOL + tid];
        #pragma unroll
        for (int r = 0; r < 16; r++) acc[r] += s[r * K + k] * w;
    }
    #pragma unroll
    for (int r = 0; r < 16; r++) {
        float v = acc[r];
        if (RELU) v = fmaxf(v, 0.f);
        out[(size_t)(r0 + r) * NCOL + tid] = v;
    }
}

__global__ void k_logsoftmax(float* __restrict__ out) {
    int g    = blockIdx.x * blockDim.x + threadIdx.x;
    int row  = g >> 5;
    int lane = g & 31;
    if (row >= N_) return;
    float v0 = out[(size_t)row * O_ + lane];
    float v1 = out[(size_t)row * O_ + 32 + lane];
    float m = fmaxf(v0, v1);
    #pragma unroll
    for (int o = 16; o; o >>= 1) m = fmaxf(m, __shfl_xor_sync(0xffffffffu, m, o));
    float s = expf(v0 - m) + expf(v1 - m);
    #pragma unroll
    for (int o = 16; o; o >>= 1) s += __shfl_xor_sync(0xffffffffu, s, o);
    float l = m + logf(s);
    out[(size_t)row * O_ + lane]      = v0 - l;
    out[(size_t)row * O_ + 32 + lane] = v1 - l;
}

// ---------------- launch ----------------
extern "C" void kernel_launch(void* const* d_in, const int* in_sizes, int n_in,
                              void* d_out, int out_size) {
    (void)in_sizes; (void)n_in; (void)out_size;
    const float* x     = (const float*)d_in[0];
    const int*   ei    = (const int*)d_in[1];     // int32 (JAX x64 disabled)
    const float* alpha = (const float*)d_in[2];
    const float* fW    = (const float*)d_in[3];
    const float* fb    = (const float*)d_in[4];
    const float* l0W   = (const float*)d_in[5];
    const float* l0b   = (const float*)d_in[6];
    const float* l1W   = (const float*)d_in[7];
    const float* l1b   = (const float*)d_in[8];
    float*       out   = (float*)d_out;

    void *p_big, *p_h1, *p_h2, *p_Abits, *p_Ax, *p_A2x;
    cudaGetSymbolAddress(&p_big,   g_big);
    cudaGetSymbolAddress(&p_h1,    g_h1);
    cudaGetSymbolAddress(&p_h2,    g_h2);
    cudaGetSymbolAddress(&p_Abits, g_Abits);
    cudaGetSymbolAddress(&p_Ax,    g_Ax);
    cudaGetSymbolAddress(&p_A2x,   g_A2x);

    // 1. adjacency bitmask
    k_clear_bits<<<(N_ * WPR + 255) / 256, 256>>>();
    k_scatter_edges<<<E_ / 256, 256>>>(ei);

    // 2. cosine sim (bf16 tensor cores) + topk
    k_rownorm<<<N_ * 32 / 128, 128>>>(x);
    k_gemm1_wmma<<<dim3(N_ / 128, N_ / 128), 256>>>();
    k_topk<<<N_, 256>>>((const float*)p_big);

    // 3. hop features + alpha aggregate (transposed, bf16)
    k_spmm<<<N_, 128>>>((const unsigned*)p_Abits, x, (float*)p_Ax);
    k_spmm<<<N_, 128>>>((const unsigned*)p_Abits, (const float*)p_Ax, (float*)p_A2x);
    k_aggT<<<dim3(C_ / 32, N_ / 32), dim3(32, 8)>>>(x, alpha);

    // 4. threefry keep-mask, force topk bits, fused mask expand + degree
    k_threefry_mask<<<HALF_ / 256, 256>>>();
    k_or_topk<<<(N_ * TOPK_ + 255) / 256, 256>>>();
    k_mask_deg<<<N_, 128>>>();

    // 5. fused_raw = Mf @ agg (bf16, split-K x8 into g_big) + deterministic reduce
    k_gemm2_wmma<<<dim3(KSPLIT, N_ / 128), 256>>>();
    k_reduce_splits<<<(N_ * C_ + 255) / 256, 256>>>();

    // 6. MLP + log_softmax
    k_mlp1<<<N_ / 16, 128>>>(x, fW, fb);
    k_mlp<128, 128, true ><<<N_ / 16, 128>>>((const float*)p_h1, l0W, l0b, (float*)p_h2);
    k_mlp<128, 64,  false><<<N_ / 16, 64 >>>((const float*)p_h2, l1W, l1b, out);
    k_logsoftmax<<<N_ * 32 / 128, 128>>>(out);
}

// round 8
// speedup vs baseline: 3.4373x; 1.0433x over previous
#include <cuda_runtime.h>
#include <cuda_bf16.h>
#include <mma.h>
using namespace nvcuda;

#define N_    4096
#define C_    128
#define H_    128
#define O_    64
#define E_    65536
#define WPR   128                 // 32-bit words per mask row (4096/32)
#define HALF_ 8388608             // N*N/2 for threefry pairing
#define TOPK_ 10
#define KSPLIT 8                  // gemm2 split-K factor

// ---------------- scratch (static device globals; no allocation) ----------------
static __device__ unsigned       g_Abits[N_ * WPR];          // 2 MB adjacency bitmask
static __device__ unsigned       g_Mbits[N_ * WPR];          // 2 MB keep-mask bitmask
static __device__ float          g_big[(size_t)N_ * N_];     // 64 MB: sim; later gemm2 partials
static __device__ __nv_bfloat16  g_xnb[N_ * C_];             // xn in bf16
static __device__ __nv_bfloat16  g_aggT[(size_t)C_ * N_];    // agg^T bf16 [C][N]
static __device__ float          g_Ax [N_ * C_];
static __device__ float          g_A2x[N_ * C_];
static __device__ float          g_h1[N_ * H_];
static __device__ float          g_h2[N_ * H_];
static __device__ int            g_topk[N_ * TOPK_];
static __device__ float          g_deg[N_];

// ---------------- adjacency ----------------
__global__ void k_clear_bits() {
    int i = blockIdx.x * blockDim.x + threadIdx.x;
    if (i < N_ * WPR) g_Abits[i] = 0u;
}

// edge_index is int32 (JAX x64 disabled downgrades int64 -> int32), layout [2, E]
__global__ void k_scatter_edges(const int* __restrict__ ei) {
    int i = blockIdx.x * blockDim.x + threadIdx.x;
    if (i >= E_) return;
    int s = ei[i];
    int d = ei[E_ + i];
    atomicOr(&g_Abits[s * WPR + (d >> 5)], 1u << (d & 31));
}

// ---------------- xn = x / (||x|| + 1e-8), stored bf16; one warp per row ----------------
__global__ void k_rownorm(const float* __restrict__ x) {
    int g    = blockIdx.x * blockDim.x + threadIdx.x;
    int row  = g >> 5;
    int lane = g & 31;
    if (row >= N_) return;
    const float4* xr = reinterpret_cast<const float4*>(x + (size_t)row * C_);
    float4 v = xr[lane];
    float s = v.x * v.x + v.y * v.y + v.z * v.z + v.w * v.w;
    #pragma unroll
    for (int o = 16; o; o >>= 1) s += __shfl_xor_sync(0xffffffffu, s, o);
    float inv = 1.0f / (sqrtf(s) + 1e-8f);
    __nv_bfloat162 p0 = __floats2bfloat162_rn(v.x * inv, v.y * inv);
    __nv_bfloat162 p1 = __floats2bfloat162_rn(v.z * inv, v.w * inv);
    __nv_bfloat162* dst = reinterpret_cast<__nv_bfloat162*>(g_xnb + (size_t)row * C_ + lane * 4);
    dst[0] = p0;
    dst[1] = p1;
}

// ---------------- GEMM1: sim = xnb @ xnb^T  (bf16 wmma, fp32 out) ----------------
#define G1PAD 16
__global__ void __launch_bounds__(256, 2) k_gemm1_wmma() {
    __shared__ __nv_bfloat16 As[128][128 + G1PAD];
    __shared__ __nv_bfloat16 Bs[128][128 + G1PAD];
    int tid = threadIdx.x;
    int m0 = blockIdx.y * 128, n0 = blockIdx.x * 128;

    #pragma unroll
    for (int it = 0; it < 8; it++) {
        int chunk = tid + 256 * it;         // 0..2047
        int r = chunk >> 4, c8 = chunk & 15;
        *reinterpret_cast<uint4*>(&As[r][c8 * 8]) =
            *reinterpret_cast<const uint4*>(g_xnb + (size_t)(m0 + r) * C_ + c8 * 8);
        *reinterpret_cast<uint4*>(&Bs[r][c8 * 8]) =
            *reinterpret_cast<const uint4*>(g_xnb + (size_t)(n0 + r) * C_ + c8 * 8);
    }
    __syncthreads();

    int w = tid >> 5;
    int wm = w >> 2, wn = w & 3;            // warp tile 64x32
    wmma::fragment<wmma::accumulator, 16, 16, 16, float> c[4][2];
    #pragma unroll
    for (int i = 0; i < 4; i++)
        #pragma unroll
        for (int j = 0; j < 2; j++) wmma::fill_fragment(c[i][j], 0.0f);

    #pragma unroll
    for (int kk = 0; kk < 8; kk++) {
        wmma::fragment<wmma::matrix_a, 16, 16, 16, __nv_bfloat16, wmma::row_major> a[4];
        wmma::fragment<wmma::matrix_b, 16, 16, 16, __nv_bfloat16, wmma::col_major> b[2];
        #pragma unroll
        for (int i = 0; i < 4; i++)
            wmma::load_matrix_sync(a[i], &As[wm * 64 + i * 16][kk * 16], 128 + G1PAD);
        #pragma unroll
        for (int j = 0; j < 2; j++)
            wmma::load_matrix_sync(b[j], &Bs[wn * 32 + j * 16][kk * 16], 128 + G1PAD);
        #pragma unroll
        for (int i = 0; i < 4; i++)
            #pragma unroll
            for (int j = 0; j < 2; j++) wmma::mma_sync(c[i][j], a[i], b[j], c[i][j]);
    }
    #pragma unroll
    for (int i = 0; i < 4; i++)
        #pragma unroll
        for (int j = 0; j < 2; j++)
            wmma::store_matrix_sync(
                g_big + (size_t)(m0 + wm * 64 + i * 16) * N_ + n0 + wn * 32 + j * 16,
                c[i][j], N_, wmma::mem_row_major);
}

// ---------------- fused: topk (blocks 0..4095) + threefry mask (rest) ----------------
__device__ __forceinline__ unsigned ford(float f) {
    unsigned u = __float_as_uint(f);
    return (u & 0x80000000u) ? ~u : (u | 0x80000000u);
}

__device__ __forceinline__ void threefry(unsigned c0, unsigned c1, unsigned& o0, unsigned& o1) {
    const unsigned k0 = 0u, k1 = 42u, k2 = 0u ^ 42u ^ 0x1BD11BDAu;
    unsigned x0 = c0 + k0, x1 = c1 + k1;
    #define TF_R(r) { x0 += x1; x1 = __funnelshift_l(x1, x1, (r)); x1 ^= x0; }
    TF_R(13) TF_R(15) TF_R(26) TF_R(6)   x0 += k1; x1 += k2 + 1u;
    TF_R(17) TF_R(29) TF_R(16) TF_R(24)  x0 += k2; x1 += k0 + 2u;
    TF_R(13) TF_R(15) TF_R(26) TF_R(6)   x0 += k0; x1 += k1 + 3u;
    TF_R(17) TF_R(29) TF_R(16) TF_R(24)  x0 += k1; x1 += k2 + 4u;
    TF_R(13) TF_R(15) TF_R(26) TF_R(6)   x0 += k2; x1 += k0 + 5u;
    #undef TF_R
    o0 = x0; o1 = x1;
}

__global__ void __launch_bounds__(256) k_topk_tf(const float* __restrict__ sim) {
    if (blockIdx.x >= N_) {
        // ---- threefry part: ALU-bound, overlaps with memory-bound topk part ----
        int t = (blockIdx.x - N_) * 256 + threadIdx.x;   // 0 .. HALF_-1
        unsigned o0, o1;
        threefry((unsigned)t, (unsigned)t + (unsigned)HALF_, o0, o1);
        unsigned m0 = __ballot_sync(0xffffffffu, !(o0 >> 31));
        unsigned m1 = __ballot_sync(0xffffffffu, !(o1 >> 31));
        int lane = threadIdx.x & 31;
        int wbase = t >> 5;                              // same for whole warp
        if (lane == 0)      g_Mbits[wbase] = m0;
        else if (lane == 1) g_Mbits[(HALF_ >> 5) + wbase] = m1;
        return;
    }
    // ---- topk part: register-resident keys, lax.top_k tie semantics ----
    __shared__ unsigned long long wbest[8];
    __shared__ unsigned long long winner;
    int row  = blockIdx.x;
    int tid  = threadIdx.x;          // 256 = 8 warps
    int w    = tid >> 5;
    int lane = tid & 31;

    unsigned long long key[16];
    #pragma unroll
    for (int i = 0; i < 16; i++) {
        int j = w * 512 + i * 32 + lane;
        float v = sim[(size_t)row * N_ + j];
        key[i] = ((unsigned long long)ford(v) << 32) | (unsigned)(N_ - 1 - j);
    }

    for (int p = 0; p < TOPK_; p++) {
        unsigned long long m = 0ull;
        #pragma unroll
        for (int i = 0; i < 16; i++) m = (key[i] > m) ? key[i] : m;
        unsigned long long wm = m;
        #pragma unroll
        for (int o = 16; o; o >>= 1) {
            unsigned long long v = __shfl_xor_sync(0xffffffffu, wm, o);
            wm = (v > wm) ? v : wm;
        }
        if (lane == 0) wbest[w] = wm;
        __syncthreads();
        if (tid < 32) {
            unsigned long long b = (tid < 8) ? wbest[tid] : 0ull;
            #pragma unroll
            for (int o = 4; o; o >>= 1) {
                unsigned long long v = __shfl_xor_sync(0xffffffffu, b, o);
                b = (v > b) ? v : b;
            }
            if (tid == 0) {
                winner = b;
                g_topk[row * TOPK_ + p] = (N_ - 1) - (int)(b & 0xffffffffull);
            }
        }
        __syncthreads();
        unsigned long long wn = winner;
        if (m == wn) {
            #pragma unroll
            for (int i = 0; i < 16; i++) if (key[i] == wn) key[i] = 0ull;
        }
        __syncthreads();
    }
}

// ---------------- sparse A*V: decode neighbor list, then ILP-4 accumulate ------------
__global__ void __launch_bounds__(128) k_spmm(const unsigned* __restrict__ bits,
                                              const float* __restrict__ V,
                                              float* __restrict__ out) {
    __shared__ unsigned short nbr[N_];   // worst-case full row, 8 KB
    __shared__ int wsum[4];
    int row = blockIdx.x, tid = threadIdx.x;   // 128 threads = 128 words = 128 cols
    int lane = tid & 31, w = tid >> 5;

    unsigned word = bits[row * WPR + tid];
    int cnt = __popc(word);
    int inc = cnt;
    #pragma unroll
    for (int o = 1; o < 32; o <<= 1) {
        int v = __shfl_up_sync(0xffffffffu, inc, o);
        if (lane >= o) inc += v;
    }
    if (lane == 31) wsum[w] = inc;
    __syncthreads();
    int base = 0;
    #pragma unroll
    for (int i = 0; i < 4; i++) if (i < w) base += wsum[i];
    int off = base + inc - cnt;
    unsigned b = word;
    while (b) {
        int t = __ffs(b) - 1;
        b &= b - 1;
        nbr[off++] = (unsigned short)((tid << 5) + t);
    }
    int nn = wsum[0] + wsum[1] + wsum[2] + wsum[3];
    __syncthreads();

    float a0 = 0.f, a1 = 0.f, a2 = 0.f, a3 = 0.f;
    int i = 0;
    for (; i + 4 <= nn; i += 4) {
        int j0 = nbr[i], j1 = nbr[i + 1], j2 = nbr[i + 2], j3 = nbr[i + 3];
        a0 += V[(size_t)j0 * C_ + tid];
        a1 += V[(size_t)j1 * C_ + tid];
        a2 += V[(size_t)j2 * C_ + tid];
        a3 += V[(size_t)j3 * C_ + tid];
    }
    for (; i < nn; i++) a0 += V[(size_t)nbr[i] * C_ + tid];
    out[(size_t)row * C_ + tid] = (a0 + a1) + (a2 + a3);
}

// ---------------- aggT[c][n] = bf16(a0*x + a1*Ax + a2*A2x)  (fused transpose) ---------
__global__ void k_aggT(const float* __restrict__ x, const float* __restrict__ alpha) {
    __shared__ float t[32][33];
    int c0 = blockIdx.x * 32, r0 = blockIdx.y * 32;
    int tx = threadIdx.x, ty = threadIdx.y; // 32 x 8
    float a0 = __ldg(&alpha[0]), a1 = __ldg(&alpha[1]), a2 = __ldg(&alpha[2]);
    #pragma unroll
    for (int i = 0; i < 4; i++) {
        size_t idx = (size_t)(r0 + ty + 8 * i) * C_ + c0 + tx;
        t[ty + 8 * i][tx] = a0 * x[idx] + a1 * g_Ax[idx] + a2 * g_A2x[idx];
    }
    __syncthreads();
    #pragma unroll
    for (int i = 0; i < 4; i++)
        g_aggT[(size_t)(c0 + ty + 8 * i) * N_ + r0 + tx] = __float2bfloat16(t[tx][ty + 8 * i]);
}

// ---------------- OR top-k bits into Mbits + row degree (no atomics) ----------------
__global__ void __launch_bounds__(128) k_or_deg() {
    __shared__ int wsum[4];
    int row = blockIdx.x, tid = threadIdx.x;   // 128 threads = 128 words
    int lane = tid & 31, w = tid >> 5;
    unsigned wd = g_Mbits[row * WPR + tid];
    #pragma unroll
    for (int p = 0; p < TOPK_; p++) {
        int j = g_topk[row * TOPK_ + p];       // broadcast load
        if ((j >> 5) == tid) wd |= 1u << (j & 31);
    }
    g_Mbits[row * WPR + tid] = wd;
    int c = __popc(wd);
    #pragma unroll
    for (int o = 16; o; o >>= 1) c += __shfl_xor_sync(0xffffffffu, c, o);
    if (lane == 0) wsum[w] = c;
    __syncthreads();
    if (tid == 0) g_deg[row] = (float)(wsum[0] + wsum[1] + wsum[2] + wsum[3]);
}

// ---------------- GEMM2 split-K with on-the-fly bf16 mask expansion ------------------
// grid (KSPLIT, 32), block 256 (8 warps 2x4). Partials land in g_big (free after topk).
#define G2PAD 16
__global__ void __launch_bounds__(256, 2) k_gemm2_wmma() {
    __shared__ __nv_bfloat16 As[128][64 + G2PAD];
    __shared__ __nv_bfloat16 Bs[128][64 + G2PAD];
    int tid = threadIdx.x;
    int split = blockIdx.x;
    int m0 = blockIdx.y * 128;
    int kbase = split * (N_ / KSPLIT);
    int w = tid >> 5;
    int wm = w >> 2, wn = w & 3;            // warp tile 64x32
    int er = tid >> 1, eh = tid & 1;        // mask-expansion row / half

    wmma::fragment<wmma::accumulator, 16, 16, 16, float> c[4][2];
    #pragma unroll
    for (int i = 0; i < 4; i++)
        #pragma unroll
        for (int j = 0; j < 2; j++) wmma::fill_fragment(c[i][j], 0.0f);

    for (int k0 = kbase; k0 < kbase + N_ / KSPLIT; k0 += 64) {
        // A tile: expand 64 mask bits per row from g_Mbits (2 words/row)
        {
            unsigned wd = g_Mbits[(m0 + er) * WPR + (k0 >> 5) + eh];
            __nv_bfloat16* dst = &As[er][eh * 32];
            #pragma unroll
            for (int gq = 0; gq < 4; gq++) {
                uint4 v;
                unsigned b = wd >> (gq * 8);
                v.x = ((b      & 1u) ? 0x3F80u : 0u) | (((b >> 1) & 1u) ? 0x3F800000u : 0u);
                v.y = (((b >> 2) & 1u) ? 0x3F80u : 0u) | (((b >> 3) & 1u) ? 0x3F800000u : 0u);
                v.z = (((b >> 4) & 1u) ? 0x3F80u : 0u) | (((b >> 5) & 1u) ? 0x3F800000u : 0u);
                v.w = (((b >> 6) & 1u) ? 0x3F80u : 0u) | (((b >> 7) & 1u) ? 0x3F800000u : 0u);
                reinterpret_cast<uint4*>(dst)[gq] = v;
            }
        }
        // B tile: aggT [C=128 rows][64 k-cols]
        #pragma unroll
        for (int it = 0; it < 4; it++) {
            int chunk = tid + 256 * it;     // 0..1023
            int r = chunk >> 3, c8 = chunk & 7;
            *reinterpret_cast<uint4*>(&Bs[r][c8 * 8]) =
                *reinterpret_cast<const uint4*>(g_aggT + (size_t)r * N_ + k0 + c8 * 8);
        }
        __syncthreads();
        #pragma unroll
        for (int kk = 0; kk < 4; kk++) {
            wmma::fragment<wmma::matrix_a, 16, 16, 16, __nv_bfloat16, wmma::row_major> a[4];
            wmma::fragment<wmma::matrix_b, 16, 16, 16, __nv_bfloat16, wmma::col_major> b[2];
            #pragma unroll
            for (int i = 0; i < 4; i++)
                wmma::load_matrix_sync(a[i], &As[wm * 64 + i * 16][kk * 16], 64 + G2PAD);
            #pragma unroll
            for (int j = 0; j < 2; j++)
                wmma::load_matrix_sync(b[j], &Bs[wn * 32 + j * 16][kk * 16], 64 + G2PAD);
            #pragma unroll
            for (int i = 0; i < 4; i++)
                #pragma unroll
                for (int j = 0; j < 2; j++) wmma::mma_sync(c[i][j], a[i], b[j], c[i][j]);
        }
        __syncthreads();
    }
    float* dst = g_big + (size_t)split * (N_ * C_);
    #pragma unroll
    for (int i = 0; i < 4; i++)
        #pragma unroll
        for (int j = 0; j < 2; j++)
            wmma::store_matrix_sync(
                dst + (size_t)(m0 + wm * 64 + i * 16) * C_ + wn * 32 + j * 16,
                c[i][j], C_, wmma::mem_row_major);
}

// ---------------- MLP (split-K reduce + deg division folded into load) ---------------
__global__ void k_mlp1(const float* __restrict__ x, const float* __restrict__ W,
                       const float* __restrict__ bias) {
    __shared__ float s[16 * 256];
    int r0 = blockIdx.x * 16, tid = threadIdx.x;  // 128 threads
    for (int i = tid; i < 16 * 128; i += 128) {
        int r = i >> 7, c = i & 127;
        float invd = 1.0f / (g_deg[r0 + r] + 1e-6f);
        float fs = 0.f;
        #pragma unroll
        for (int k = 0; k < KSPLIT; k++)
            fs += g_big[(size_t)k * (N_ * C_) + (size_t)(r0 + r) * C_ + c];
        s[r * 256 + c]       = x[(size_t)(r0 + r) * 128 + c];
        s[r * 256 + 128 + c] = fs * invd;
    }
    __syncthreads();
    float acc[16];
    float bb = bias[tid];
    #pragma unroll
    for (int r = 0; r < 16; r++) acc[r] = bb;
    for (int k = 0; k < 256; k++) {
        float w = W[k * 128 + tid];
        #pragma unroll
        for (int r = 0; r < 16; r++) acc[r] += s[r * 256 + k] * w;
    }
    #pragma unroll
    for (int r = 0; r < 16; r++) g_h1[(size_t)(r0 + r) * 128 + tid] = acc[r];
}

template<int K, int NCOL, bool RELU>
__global__ void k_mlp(const float* __restrict__ in, const float* __restrict__ W,
                      const float* __restrict__ bias, float* __restrict__ out) {
    __shared__ float s[16 * K];
    int r0 = blockIdx.x * 16, tid = threadIdx.x;  // NCOL threads
    for (int i = tid; i < 16 * K; i += NCOL) s[i] = in[(size_t)r0 * K + i];
    __syncthreads();
    float acc[16];
    float bb = bias[tid];
    #pragma unroll
    for (int r = 0; r < 16; r++) acc[r] = bb;
    for (int k = 0; k < K; k++) {
        float w = W[k * NCOL + tid];
        #pragma unroll
        for (int r = 0; r < 16; r++) acc[r] += s[r * K + k] * w;
    }
    #pragma unroll
    for (int r = 0; r < 16; r++) {
        float v = acc[r];
        if (RELU) v = fmaxf(v, 0.f);
        out[(size_t)(r0 + r) * NCOL + tid] = v;
    }
}

__global__ void k_logsoftmax(float* __restrict__ out) {
    int g    = blockIdx.x * blockDim.x + threadIdx.x;
    int row  = g >> 5;
    int lane = g & 31;
    if (row >= N_) return;
    float v0 = out[(size_t)row * O_ + lane];
    float v1 = out[(size_t)row * O_ + 32 + lane];
    float m = fmaxf(v0, v1);
    #pragma unroll
    for (int o = 16; o; o >>= 1) m = fmaxf(m, __shfl_xor_sync(0xffffffffu, m, o));
    float s = expf(v0 - m) + expf(v1 - m);
    #pragma unroll
    for (int o = 16; o; o >>= 1) s += __shfl_xor_sync(0xffffffffu, s, o);
    float l = m + logf(s);
    out[(size_t)row * O_ + lane]      = v0 - l;
    out[(size_t)row * O_ + 32 + lane] = v1 - l;
}

// ---------------- launch ----------------
extern "C" void kernel_launch(void* const* d_in, const int* in_sizes, int n_in,
                              void* d_out, int out_size) {
    (void)in_sizes; (void)n_in; (void)out_size;
    const float* x     = (const float*)d_in[0];
    const int*   ei    = (const int*)d_in[1];     // int32 (JAX x64 disabled)
    const float* alpha = (const float*)d_in[2];
    const float* fW    = (const float*)d_in[3];
    const float* fb    = (const float*)d_in[4];
    const float* l0W   = (const float*)d_in[5];
    const float* l0b   = (const float*)d_in[6];
    const float* l1W   = (const float*)d_in[7];
    const float* l1b   = (const float*)d_in[8];
    float*       out   = (float*)d_out;

    void *p_big, *p_h1, *p_h2, *p_Abits, *p_Ax, *p_A2x;
    cudaGetSymbolAddress(&p_big,   g_big);
    cudaGetSymbolAddress(&p_h1,    g_h1);
    cudaGetSymbolAddress(&p_h2,    g_h2);
    cudaGetSymbolAddress(&p_Abits, g_Abits);
    cudaGetSymbolAddress(&p_Ax,    g_Ax);
    cudaGetSymbolAddress(&p_A2x,   g_A2x);

    // 1. adjacency bitmask
    k_clear_bits<<<(N_ * WPR + 255) / 256, 256>>>();
    k_scatter_edges<<<E_ / 256, 256>>>(ei);

    // 2. cosine sim (bf16 tensor cores)
    k_rownorm<<<N_ * 32 / 128, 128>>>(x);
    k_gemm1_wmma<<<dim3(N_ / 128, N_ / 128), 256>>>();

    // 3. hop features + alpha aggregate (transposed, bf16)
    k_spmm<<<N_, 128>>>((const unsigned*)p_Abits, x, (float*)p_Ax);
    k_spmm<<<N_, 128>>>((const unsigned*)p_Abits, (const float*)p_Ax, (float*)p_A2x);
    k_aggT<<<dim3(C_ / 32, N_ / 32), dim3(32, 8)>>>(x, alpha);

    // 4. fused: topk (mem-bound) + threefry keep-mask (ALU-bound) — overlapped
    k_topk_tf<<<N_ + HALF_ / 256, 256>>>((const float*)p_big);

    // 5. OR topk bits + degree (no atomics)
    k_or_deg<<<N_, 128>>>();

    // 6. fused_raw = Mf @ agg (bf16 split-K x8, mask expanded from bits in-kernel)
    k_gemm2_wmma<<<dim3(KSPLIT, N_ / 128), 256>>>();

    // 7. MLP (split-K reduce + deg-div folded into k_mlp1) + log_softmax
    k_mlp1<<<N_ / 16, 128>>>(x, fW, fb);
    k_mlp<128, 128, true ><<<N_ / 16, 128>>>((const float*)p_h1, l0W, l0b, (float*)p_h2);
    k_mlp<128, 64,  false><<<N_ / 16, 64 >>>((const float*)p_h2, l1W, l1b, out);
    k_logsoftmax<<<N_ * 32 / 128, 128>>>(out);
}

// round 13
// speedup vs baseline: 3.8797x; 1.1287x over previous
#include <cuda_runtime.h>
#include <cuda_bf16.h>
#include <mma.h>
using namespace nvcuda;

#define N_    4096
#define C_    128
#define H_    128
#define O_    64
#define E_    65536
#define WPR   128                 // 32-bit words per mask row (4096/32)
#define HALF_ 8388608             // N*N/2 for threefry pairing
#define TOPK_ 10
#define KSPLIT 8                  // gemm2 split-K factor
#define NT_   32                  // 128-tiles per dim
#define NTRI  528                 // NT_*(NT_+1)/2

// ---------------- scratch (static device globals; no allocation) ----------------
static __device__ unsigned       g_Abits[N_ * WPR];          // 2 MB adjacency bitmask
static __device__ unsigned       g_Mbits[N_ * WPR];          // 2 MB keep-mask bitmask
static __device__ float          g_big[(size_t)N_ * N_];     // 64 MB: sim; later gemm2 partials
static __device__ __nv_bfloat16  g_xnb[N_ * C_];             // xn in bf16
static __device__ __nv_bfloat16  g_aggT[(size_t)C_ * N_];    // agg^T bf16 [C][N]
static __device__ float          g_Ax [N_ * C_];
static __device__ float          g_A2x[N_ * C_];
static __device__ int            g_topk[N_ * TOPK_];
static __device__ float          g_deg[N_];

// ---------------- fused: scatter edges (blocks 0..255) + rownorm (256..767) ----------
// edge_index is int32 (JAX x64 disabled downgrades int64 -> int32), layout [2, E]
__global__ void __launch_bounds__(256) k_pre(const int* __restrict__ ei,
                                             const float* __restrict__ x) {
    if (blockIdx.x < E_ / 256) {
        int i = blockIdx.x * 256 + threadIdx.x;
        int s = ei[i];
        int d = ei[E_ + i];
        atomicOr(&g_Abits[s * WPR + (d >> 5)], 1u << (d & 31));
        return;
    }
    // rownorm: xn = x / (||x|| + 1e-8), bf16; one warp per row
    int g    = (blockIdx.x - E_ / 256) * 256 + threadIdx.x;
    int row  = g >> 5;
    int lane = g & 31;
    if (row >= N_) return;
    const float4* xr = reinterpret_cast<const float4*>(x + (size_t)row * C_);
    float4 v = xr[lane];
    float s = v.x * v.x + v.y * v.y + v.z * v.z + v.w * v.w;
    #pragma unroll
    for (int o = 16; o; o >>= 1) s += __shfl_xor_sync(0xffffffffu, s, o);
    float inv = 1.0f / (sqrtf(s) + 1e-8f);
    __nv_bfloat162 p0 = __floats2bfloat162_rn(v.x * inv, v.y * inv);
    __nv_bfloat162 p1 = __floats2bfloat162_rn(v.z * inv, v.w * inv);
    __nv_bfloat162* dst = reinterpret_cast<__nv_bfloat162*>(g_xnb + (size_t)row * C_ + lane * 4);
    dst[0] = p0;
    dst[1] = p1;
}

// ---------------- GEMM1 (symmetric): sim = xnb @ xnb^T, upper-tri tiles only ---------
#define G1PAD 16
__global__ void __launch_bounds__(256, 2) k_gemm1_wmma() {
    __shared__ __nv_bfloat16 As[128][128 + G1PAD];
    __shared__ __nv_bfloat16 Bs[128][128 + G1PAD];
    int tid = threadIdx.x;

    // triangular decode: tile (bm, bn), bm <= bn
    int idx = blockIdx.x;
    int bm = 0;
    while ((bm + 1) * NT_ - ((bm + 1) * bm) / 2 <= idx) bm++;
    int bn = bm + idx - (bm * NT_ - (bm * (bm - 1)) / 2);
    int m0 = bm * 128, n0 = bn * 128;

    #pragma unroll
    for (int it = 0; it < 8; it++) {
        int chunk = tid + 256 * it;         // 0..2047
        int r = chunk >> 4, c8 = chunk & 15;
        *reinterpret_cast<uint4*>(&As[r][c8 * 8]) =
            *reinterpret_cast<const uint4*>(g_xnb + (size_t)(m0 + r) * C_ + c8 * 8);
        *reinterpret_cast<uint4*>(&Bs[r][c8 * 8]) =
            *reinterpret_cast<const uint4*>(g_xnb + (size_t)(n0 + r) * C_ + c8 * 8);
    }
    __syncthreads();

    int w = tid >> 5;
    int wm = w >> 2, wn = w & 3;            // warp tile 64x32
    wmma::fragment<wmma::accumulator, 16, 16, 16, float> c[4][2];
    #pragma unroll
    for (int i = 0; i < 4; i++)
        #pragma unroll
        for (int j = 0; j < 2; j++) wmma::fill_fragment(c[i][j], 0.0f);

    #pragma unroll
    for (int kk = 0; kk < 8; kk++) {
        wmma::fragment<wmma::matrix_a, 16, 16, 16, __nv_bfloat16, wmma::row_major> a[4];
        wmma::fragment<wmma::matrix_b, 16, 16, 16, __nv_bfloat16, wmma::col_major> b[2];
        #pragma unroll
        for (int i = 0; i < 4; i++)
            wmma::load_matrix_sync(a[i], &As[wm * 64 + i * 16][kk * 16], 128 + G1PAD);
        #pragma unroll
        for (int j = 0; j < 2; j++)
            wmma::load_matrix_sync(b[j], &Bs[wn * 32 + j * 16][kk * 16], 128 + G1PAD);
        #pragma unroll
        for (int i = 0; i < 4; i++)
            #pragma unroll
            for (int j = 0; j < 2; j++) wmma::mma_sync(c[i][j], a[i], b[j], c[i][j]);
    }
    #pragma unroll
    for (int i = 0; i < 4; i++)
        #pragma unroll
        for (int j = 0; j < 2; j++) {
            int mr = m0 + wm * 64 + i * 16;
            int nc = n0 + wn * 32 + j * 16;
            wmma::store_matrix_sync(g_big + (size_t)mr * N_ + nc, c[i][j], N_,
                                    wmma::mem_row_major);
            if (bm != bn)   // mirrored tile: col-major store = transpose
                wmma::store_matrix_sync(g_big + (size_t)nc * N_ + mr, c[i][j], N_,
                                        wmma::mem_col_major);
        }
}

// ---------------- fused: topk (blocks 0..4095) + threefry mask (rest) ----------------
__device__ __forceinline__ unsigned ford(float f) {
    unsigned u = __float_as_uint(f);
    return (u & 0x80000000u) ? ~u : (u | 0x80000000u);
}

__device__ __forceinline__ void threefry(unsigned c0, unsigned c1, unsigned& o0, unsigned& o1) {
    const unsigned k0 = 0u, k1 = 42u, k2 = 0u ^ 42u ^ 0x1BD11BDAu;
    unsigned x0 = c0 + k0, x1 = c1 + k1;
    #define TF_R(r) { x0 += x1; x1 = __funnelshift_l(x1, x1, (r)); x1 ^= x0; }
    TF_R(13) TF_R(15) TF_R(26) TF_R(6)   x0 += k1; x1 += k2 + 1u;
    TF_R(17) TF_R(29) TF_R(16) TF_R(24)  x0 += k2; x1 += k0 + 2u;
    TF_R(13) TF_R(15) TF_R(26) TF_R(6)   x0 += k0; x1 += k1 + 3u;
    TF_R(17) TF_R(29) TF_R(16) TF_R(24)  x0 += k1; x1 += k2 + 4u;
    TF_R(13) TF_R(15) TF_R(26) TF_R(6)   x0 += k2; x1 += k0 + 5u;
    #undef TF_R
    o0 = x0; o1 = x1;
}

__global__ void __launch_bounds__(256) k_topk_tf(const float* __restrict__ sim) {
    if (blockIdx.x >= N_) {
        int t = (blockIdx.x - N_) * 256 + threadIdx.x;   // 0 .. HALF_-1
        unsigned o0, o1;
        threefry((unsigned)t, (unsigned)t + (unsigned)HALF_, o0, o1);
        unsigned m0 = __ballot_sync(0xffffffffu, !(o0 >> 31));
        unsigned m1 = __ballot_sync(0xffffffffu, !(o1 >> 31));
        int lane = threadIdx.x & 31;
        int wbase = t >> 5;
        if (lane == 0)      g_Mbits[wbase] = m0;
        else if (lane == 1) g_Mbits[(HALF_ >> 5) + wbase] = m1;
        return;
    }
    __shared__ unsigned long long wbest[8];
    __shared__ unsigned long long winner;
    int row  = blockIdx.x;
    int tid  = threadIdx.x;          // 256 = 8 warps
    int w    = tid >> 5;
    int lane = tid & 31;

    unsigned long long key[16];
    #pragma unroll
    for (int i = 0; i < 16; i++) {
        int j = w * 512 + i * 32 + lane;
        float v = sim[(size_t)row * N_ + j];
        key[i] = ((unsigned long long)ford(v) << 32) | (unsigned)(N_ - 1 - j);
    }

    for (int p = 0; p < TOPK_; p++) {
        unsigned long long m = 0ull;
        #pragma unroll
        for (int i = 0; i < 16; i++) m = (key[i] > m) ? key[i] : m;
        unsigned long long wm = m;
        #pragma unroll
        for (int o = 16; o; o >>= 1) {
            unsigned long long v = __shfl_xor_sync(0xffffffffu, wm, o);
            wm = (v > wm) ? v : wm;
        }
        if (lane == 0) wbest[w] = wm;
        __syncthreads();
        if (tid < 32) {
            unsigned long long b = (tid < 8) ? wbest[tid] : 0ull;
            #pragma unroll
            for (int o = 4; o; o >>= 1) {
                unsigned long long v = __shfl_xor_sync(0xffffffffu, b, o);
                b = (v > b) ? v : b;
            }
            if (tid == 0) {
                winner = b;
                g_topk[row * TOPK_ + p] = (N_ - 1) - (int)(b & 0xffffffffull);
            }
        }
        __syncthreads();
        unsigned long long wn = winner;
        if (m == wn) {
            #pragma unroll
            for (int i = 0; i < 16; i++) if (key[i] == wn) key[i] = 0ull;
        }
        __syncthreads();
    }
}

// ---------------- sparse A*V: decode neighbor list, then ILP-4 accumulate ------------
__global__ void __launch_bounds__(128) k_spmm(const unsigned* __restrict__ bits,
                                              const float* __restrict__ V,
                                              float* __restrict__ out) {
    __shared__ unsigned short nbr[N_];
    __shared__ int wsum[4];
    int row = blockIdx.x, tid = threadIdx.x;   // 128 threads = 128 words = 128 cols
    int lane = tid & 31, w = tid >> 5;

    unsigned word = bits[row * WPR + tid];
    int cnt = __popc(word);
    int inc = cnt;
    #pragma unroll
    for (int o = 1; o < 32; o <<= 1) {
        int v = __shfl_up_sync(0xffffffffu, inc, o);
        if (lane >= o) inc += v;
    }
    if (lane == 31) wsum[w] = inc;
    __syncthreads();
    int base = 0;
    #pragma unroll
    for (int i = 0; i < 4; i++) if (i < w) base += wsum[i];
    int off = base + inc - cnt;
    unsigned b = word;
    while (b) {
        int t = __ffs(b) - 1;
        b &= b - 1;
        nbr[off++] = (unsigned short)((tid << 5) + t);
    }
    int nn = wsum[0] + wsum[1] + wsum[2] + wsum[3];
    __syncthreads();

    float a0 = 0.f, a1 = 0.f, a2 = 0.f, a3 = 0.f;
    int i = 0;
    for (; i + 4 <= nn; i += 4) {
        int j0 = nbr[i], j1 = nbr[i + 1], j2 = nbr[i + 2], j3 = nbr[i + 3];
        a0 += V[(size_t)j0 * C_ + tid];
        a1 += V[(size_t)j1 * C_ + tid];
        a2 += V[(size_t)j2 * C_ + tid];
        a3 += V[(size_t)j3 * C_ + tid];
    }
    for (; i < nn; i++) a0 += V[(size_t)nbr[i] * C_ + tid];
    out[(size_t)row * C_ + tid] = (a0 + a1) + (a2 + a3);
}

// ---------------- fused: aggT transpose (blocks 0..511) + or_deg (512..4607) ---------
__global__ void __launch_bounds__(256) k_aggT_ordeg(const float* __restrict__ x,
                                                    const float* __restrict__ alpha) {
    if (blockIdx.x < 512) {
        // aggT[c][n] = bf16(a0*x + a1*Ax + a2*A2x), 32x32 tile transpose
        __shared__ float t[32][33];
        int bx = blockIdx.x & 3, by = blockIdx.x >> 2;     // (C_/32, N_/32)
        int c0 = bx * 32, r0 = by * 32;
        int tx = threadIdx.x & 31, ty = threadIdx.x >> 5;  // 32 x 8
        float a0 = __ldg(&alpha[0]), a1 = __ldg(&alpha[1]), a2 = __ldg(&alpha[2]);
        #pragma unroll
        for (int i = 0; i < 4; i++) {
            size_t idx = (size_t)(r0 + ty + 8 * i) * C_ + c0 + tx;
            t[ty + 8 * i][tx] = a0 * x[idx] + a1 * g_Ax[idx] + a2 * g_A2x[idx];
        }
        __syncthreads();
        #pragma unroll
        for (int i = 0; i < 4; i++)
            g_aggT[(size_t)(c0 + ty + 8 * i) * N_ + r0 + tx] =
                __float2bfloat16(t[tx][ty + 8 * i]);
        return;
    }
    // or_deg: OR top-k bits into Mbits + row degree (no atomics); first 128 threads
    __shared__ int wsum[4];
    int row = blockIdx.x - 512, tid = threadIdx.x;
    if (tid < 128) {
        int lane = tid & 31, w = tid >> 5;
        unsigned wd = g_Mbits[row * WPR + tid];
        #pragma unroll
        for (int p = 0; p < TOPK_; p++) {
            int j = g_topk[row * TOPK_ + p];
            if ((j >> 5) == tid) wd |= 1u << (j & 31);
        }
        g_Mbits[row * WPR + tid] = wd;
        int c = __popc(wd);
        #pragma unroll
        for (int o = 16; o; o >>= 1) c += __shfl_xor_sync(0xffffffffu, c, o);
        if (lane == 0) wsum[w] = c;
    }
    __syncthreads();
    if (tid == 0) g_deg[row] = (float)(wsum[0] + wsum[1] + wsum[2] + wsum[3]);
}

// ---------------- GEMM2 split-K with on-the-fly bf16 mask expansion ------------------
#define G2PAD 16
__global__ void __launch_bounds__(256, 2) k_gemm2_wmma() {
    __shared__ __nv_bfloat16 As[128][64 + G2PAD];
    __shared__ __nv_bfloat16 Bs[128][64 + G2PAD];
    int tid = threadIdx.x;
    int split = blockIdx.x;
    int m0 = blockIdx.y * 128;
    int kbase = split * (N_ / KSPLIT);
    int w = tid >> 5;
    int wm = w >> 2, wn = w & 3;
    int er = tid >> 1, eh = tid & 1;

    wmma::fragment<wmma::accumulator, 16, 16, 16, float> c[4][2];
    #pragma unroll
    for (int i = 0; i < 4; i++)
        #pragma unroll
        for (int j = 0; j < 2; j++) wmma::fill_fragment(c[i][j], 0.0f);

    for (int k0 = kbase; k0 < kbase + N_ / KSPLIT; k0 += 64) {
        {
            unsigned wd = g_Mbits[(m0 + er) * WPR + (k0 >> 5) + eh];
            __nv_bfloat16* dst = &As[er][eh * 32];
            #pragma unroll
            for (int gq = 0; gq < 4; gq++) {
                uint4 v;
                unsigned b = wd >> (gq * 8);
                v.x = ((b      & 1u) ? 0x3F80u : 0u) | (((b >> 1) & 1u) ? 0x3F800000u : 0u);
                v.y = (((b >> 2) & 1u) ? 0x3F80u : 0u) | (((b >> 3) & 1u) ? 0x3F800000u : 0u);
                v.z = (((b >> 4) & 1u) ? 0x3F80u : 0u) | (((b >> 5) & 1u) ? 0x3F800000u : 0u);
                v.w = (((b >> 6) & 1u) ? 0x3F80u : 0u) | (((b >> 7) & 1u) ? 0x3F800000u : 0u);
                reinterpret_cast<uint4*>(dst)[gq] = v;
            }
        }
        #pragma unroll
        for (int it = 0; it < 4; it++) {
            int chunk = tid + 256 * it;
            int r = chunk >> 3, c8 = chunk & 7;
            *reinterpret_cast<uint4*>(&Bs[r][c8 * 8]) =
                *reinterpret_cast<const uint4*>(g_aggT + (size_t)r * N_ + k0 + c8 * 8);
        }
        __syncthreads();
        #pragma unroll
        for (int kk = 0; kk < 4; kk++) {
            wmma::fragment<wmma::matrix_a, 16, 16, 16, __nv_bfloat16, wmma::row_major> a[4];
            wmma::fragment<wmma::matrix_b, 16, 16, 16, __nv_bfloat16, wmma::col_major> b[2];
            #pragma unroll
            for (int i = 0; i < 4; i++)
                wmma::load_matrix_sync(a[i], &As[wm * 64 + i * 16][kk * 16], 64 + G2PAD);
            #pragma unroll
            for (int j = 0; j < 2; j++)
                wmma::load_matrix_sync(b[j], &Bs[wn * 32 + j * 16][kk * 16], 64 + G2PAD);
            #pragma unroll
            for (int i = 0; i < 4; i++)
                #pragma unroll
                for (int j = 0; j < 2; j++) wmma::mma_sync(c[i][j], a[i], b[j], c[i][j]);
        }
        __syncthreads();
    }
    float* dst = g_big + (size_t)split * (N_ * C_);
    #pragma unroll
    for (int i = 0; i < 4; i++)
        #pragma unroll
        for (int j = 0; j < 2; j++)
            wmma::store_matrix_sync(
                dst + (size_t)(m0 + wm * 64 + i * 16) * C_ + wn * 32 + j * 16,
                c[i][j], C_, wmma::mem_row_major);
}

// ---------------- fused 3-layer MLP (split-K reduce + deg-div folded in) -------------
__global__ void __launch_bounds__(128) k_mlp_fused(
    const float* __restrict__ x,
    const float* __restrict__ fW,  const float* __restrict__ fb,
    const float* __restrict__ l0W, const float* __restrict__ l0b,
    const float* __restrict__ l1W, const float* __restrict__ l1b,
    float* __restrict__ out) {
    __shared__ float s1[16 * 256];     // concat input
    __shared__ float sh[16 * 128];     // h1 then h2
    int r0 = blockIdx.x * 16, tid = threadIdx.x;  // 128 threads

    // stage 0: build concat [x | fused/deg]
    for (int i = tid; i < 16 * 128; i += 128) {
        int r = i >> 7, c = i & 127;
        float invd = 1.0f / (g_deg[r0 + r] + 1e-6f);
        float fs = 0.f;
        #pragma unroll
        for (int k = 0; k < KSPLIT; k++)
            fs += g_big[(size_t)k * (N_ * C_) + (size_t)(r0 + r) * C_ + c];
        s1[r * 256 + c]       = x[(size_t)(r0 + r) * 128 + c];
        s1[r * 256 + 128 + c] = fs * invd;
    }
    __syncthreads();

    // stage 1: h1 = concat @ fW + fb   (col = tid)
    {
        float acc[16];
        float bb = fb[tid];
        #pragma unroll
        for (int r = 0; r < 16; r++) acc[r] = bb;
        for (int k = 0; k < 256; k++) {
            float wv = fW[k * 128 + tid];
            #pragma unroll
            for (int r = 0; r < 16; r++) acc[r] += s1[r * 256 + k] * wv;
        }
        #pragma unroll
        for (int r = 0; r < 16; r++) sh[r * 128 + tid] = acc[r];
    }
    __syncthreads();

    // stage 2: h2 = relu(h1 @ l0W + l0b)
    {
        float acc[16];
        float bb = l0b[tid];
        #pragma unroll
        for (int r = 0; r < 16; r++) acc[r] = bb;
        for (int k = 0; k < 128; k++) {
            float wv = l0W[k * 128 + tid];
            #pragma unroll
            for (int r = 0; r < 16; r++) acc[r] += sh[r * 128 + k] * wv;
        }
        __syncthreads();
        #pragma unroll
        for (int r = 0; r < 16; r++) sh[r * 128 + tid] = fmaxf(acc[r], 0.f);
    }
    __syncthreads();

    // stage 3: logits = h2 @ l1W + l1b  (64 cols; tid -> col tid&63, rows split by tid>>6)
    {
        int col  = tid & 63;
        int half = tid >> 6;          // 0/1 -> rows [0..7] / [8..15]
        float acc[8];
        float bb = l1b[col];
        #pragma unroll
        for (int q = 0; q < 8; q++) acc[q] = bb;
        for (int k = 0; k < 128; k++) {
            float wv = l1W[k * 64 + col];
            #pragma unroll
            for (int q = 0; q < 8; q++) acc[q] += sh[(half * 8 + q) * 128 + k] * wv;
        }
        #pragma unroll
        for (int q = 0; q < 8; q++)
            out[(size_t)(r0 + half * 8 + q) * O_ + col] = acc[q];
    }
}

// ---------------- log_softmax (in place) + clear Abits for next replay ---------------
__global__ void __launch_bounds__(128) k_lsm_clear(float* __restrict__ out) {
    int g    = blockIdx.x * blockDim.x + threadIdx.x;
    int row  = g >> 5;
    int lane = g & 31;
    float v0 = out[(size_t)row * O_ + lane];
    float v1 = out[(size_t)row * O_ + 32 + lane];
    float m = fmaxf(v0, v1);
    #pragma unroll
    for (int o = 16; o; o >>= 1) m = fmaxf(m, __shfl_xor_sync(0xffffffffu, m, o));
    float s = expf(v0 - m) + expf(v1 - m);
    #pragma unroll
    for (int o = 16; o; o >>= 1) s += __shfl_xor_sync(0xffffffffu, s, o);
    float l = m + logf(s);
    out[(size_t)row * O_ + lane]      = v0 - l;
    out[(size_t)row * O_ + 32 + lane] = v1 - l;
    // clear adjacency bitmask for the next graph replay (statics start zeroed)
    #pragma unroll
    for (int i = 0; i < 4; i++) g_Abits[g + i * (N_ * 32)] = 0u;
}

// ---------------- launch ----------------
extern "C" void kernel_launch(void* const* d_in, const int* in_sizes, int n_in,
                              void* d_out, int out_size) {
    (void)in_sizes; (void)n_in; (void)out_size;
    const float* x     = (const float*)d_in[0];
    const int*   ei    = (const int*)d_in[1];     // int32 (JAX x64 disabled)
    const float* alpha = (const float*)d_in[2];
    const float* fW    = (const float*)d_in[3];
    const float* fb    = (const float*)d_in[4];
    const float* l0W   = (const float*)d_in[5];
    const float* l0b   = (const float*)d_in[6];
    const float* l1W   = (const float*)d_in[7];
    const float* l1b   = (const float*)d_in[8];
    float*       out   = (float*)d_out;

    void *p_big, *p_Abits, *p_Ax, *p_A2x;
    cudaGetSymbolAddress(&p_big,   g_big);
    cudaGetSymbolAddress(&p_Abits, g_Abits);
    cudaGetSymbolAddress(&p_Ax,    g_Ax);
    cudaGetSymbolAddress(&p_A2x,   g_A2x);

    // 1. scatter edges + rownorm (fused)
    k_pre<<<E_ / 256 + N_ * 32 / 256, 256>>>(ei, x);

    // 2. cosine sim, symmetric tiles only (bf16 tensor cores)
    k_gemm1_wmma<<<NTRI, 256>>>();

    // 3. hop features
    k_spmm<<<N_, 128>>>((const unsigned*)p_Abits, x, (float*)p_Ax);
    k_spmm<<<N_, 128>>>((const unsigned*)p_Abits, (const float*)p_Ax, (float*)p_A2x);

    // 4. fused: topk (mem-bound) + threefry keep-mask (ALU-bound)
    k_topk_tf<<<N_ + HALF_ / 256, 256>>>((const float*)p_big);

    // 5. fused: aggT transpose + OR-topk/degree
    k_aggT_ordeg<<<512 + N_, 256>>>(x, alpha);

    // 6. fused_raw = Mf @ agg (bf16 split-K x8, mask expanded from bits in-kernel)
    k_gemm2_wmma<<<dim3(KSPLIT, N_ / 128), 256>>>();

    // 7. fused 3-layer MLP
    k_mlp_fused<<<N_ / 16, 128>>>(x, fW, fb, l0W, l0b, l1W, l1b, out);

    // 8. log_softmax + clear Abits for next replay
    k_lsm_clear<<<N_ * 32 / 128, 128>>>(out);
}